// round 13
// baseline (speedup 1.0000x reference)
#include <cuda_runtime.h>
#include <cuda_bf16.h>
#include <cstdint>
#include <math.h>

#define TOK 20000      // 2 * 16 windows * 625 tokens
#define DCH 256
#define QKVN 768
#define HID 512

typedef unsigned short ush;

// ---- scratch: plain bf16 planes ----
__device__ ush g_xw  [TOK * DCH];   // gather out / QKV in ; later out-proj out
__device__ ush g_qkv [TOK * QKVN];
__device__ ush g_att [TOK * DCH];   // attn out / out-proj in
__device__ ush g_ln  [TOK * DCH];
__device__ ush g_hid [TOK * HID];
// all four weight matrices concatenated: wqkv | wout | w1 | w2
#define WQ 0
#define WO 196608
#define W1 262144
#define W2 393216
#define WTOT 524288
__device__ ush g_w[WTOT];

// ---------------------------------------------------------------------------
// helpers
// ---------------------------------------------------------------------------
__device__ __forceinline__ uint32_t smem_u32(const void* p) {
    uint32_t a;
    asm("{ .reg .u64 t; cvta.to.shared.u64 t, %1; cvt.u32.u64 %0, t; }" : "=r"(a) : "l"(p));
    return a;
}
#define CP_ASYNC16(dst, src) \
    asm volatile("cp.async.cg.shared.global [%0], [%1], 16;" :: "r"(dst), "l"(src))
#define CP_COMMIT() asm volatile("cp.async.commit_group;")
#define CP_WAIT1()  asm volatile("cp.async.wait_group 1;")
#define CP_WAIT0()  asm volatile("cp.async.wait_group 0;")

__device__ __forceinline__ void ldm_x4(uint32_t& d0, uint32_t& d1, uint32_t& d2,
                                       uint32_t& d3, uint32_t addr)
{
    asm volatile("ldmatrix.sync.aligned.m8n8.x4.shared.b16 {%0,%1,%2,%3}, [%4];"
                 : "=r"(d0), "=r"(d1), "=r"(d2), "=r"(d3) : "r"(addr));
}
__device__ __forceinline__ void ldm_x4t(uint32_t& d0, uint32_t& d1, uint32_t& d2,
                                        uint32_t& d3, uint32_t addr)
{
    asm volatile("ldmatrix.sync.aligned.m8n8.x4.trans.shared.b16 {%0,%1,%2,%3}, [%4];"
                 : "=r"(d0), "=r"(d1), "=r"(d2), "=r"(d3) : "r"(addr));
}

__device__ __forceinline__ void mma16816(float c[4], uint32_t a0, uint32_t a1,
                                         uint32_t a2, uint32_t a3,
                                         uint32_t b0, uint32_t b1)
{
    asm volatile(
        "mma.sync.aligned.m16n8k16.row.col.f32.bf16.bf16.f32 "
        "{%0,%1,%2,%3}, {%4,%5,%6,%7}, {%8,%9}, {%0,%1,%2,%3};"
        : "+f"(c[0]), "+f"(c[1]), "+f"(c[2]), "+f"(c[3])
        : "r"(a0), "r"(a1), "r"(a2), "r"(a3), "r"(b0), "r"(b1));
}

__device__ __forceinline__ ush bfr(float f) {
    return __bfloat16_as_ushort(__float2bfloat16_rn(f));
}
// pack 2 floats -> bf16x2 in ONE cvt (lo = first arg)
__device__ __forceinline__ uint32_t pack2bf(float lo, float hi) {
    uint32_t r;
    asm("cvt.rn.bf16x2.f32 %0, %1, %2;" : "=r"(r) : "f"(hi), "f"(lo));
    return r;
}
// packed exp2 on bf16x2
__device__ __forceinline__ uint32_t ex2_bf16x2(uint32_t x) {
    uint32_t r;
    asm("ex2.approx.ftz.bf16x2 %0, %1;" : "=r"(r) : "r"(x));
    return r;
}
__device__ __forceinline__ float lo_bf(uint32_t w) { return __uint_as_float(w << 16); }
__device__ __forceinline__ float hi_bf(uint32_t w) { return __uint_as_float(w & 0xFFFF0000u); }

__device__ __forceinline__ float gelu_exact(float v)
{
    return 0.5f * v * (1.0f + erff(v * 0.70710678118654752f));
}

// ---------------------------------------------------------------------------
// merged weight conversion
// ---------------------------------------------------------------------------
__global__ __launch_bounds__(256) void cvt4_kernel(
    const float* __restrict__ s0, const float* __restrict__ s1,
    const float* __restrict__ s2, const float* __restrict__ s3,
    ush* __restrict__ h)
{
    int base = (blockIdx.x * blockDim.x + threadIdx.x) * 4;
    if (base >= WTOT) return;
    const float* src;
    int off;
    if (base < WO)      { src = s0; off = base; }
    else if (base < W1) { src = s1; off = base - WO; }
    else if (base < W2) { src = s2; off = base - W1; }
    else                { src = s3; off = base - W2; }
    float4 v = *(const float4*)(src + off);
    uint2 o;
    o.x = pack2bf(v.x, v.y);
    o.y = pack2bf(v.z, v.w);
    *(uint2*)(h + base) = o;
}

// ---------------------------------------------------------------------------
// window partition with smem transpose: x (2,256,100,100) -> bf16 (20000,256)
// ---------------------------------------------------------------------------
__global__ __launch_bounds__(256) void gather_kernel(const float* __restrict__ x,
                                                     ush* __restrict__ xh)
{
    __shared__ float sm[32][33];
    const int w = threadIdx.x >> 5, lane = threadIdx.x & 31;
    const int tk0 = blockIdx.x * 32;
    const int ch0 = blockIdx.y * 32;

    {
        int tk = tk0 + lane;
        int bb = tk / 10000, rr = tk % 10000;
        int win = rr / 625, t = rr % 625;
        int hh = (win >> 2) * 25 + t / 25;
        int ww = (win & 3) * 25 + t % 25;
        int base = bb * 2560000 + hh * 100 + ww;
#pragma unroll
        for (int i = 0; i < 4; i++) {
            int ch = ch0 + w * 4 + i;
            sm[w * 4 + i][lane] = x[base + ch * 10000];
        }
    }
    __syncthreads();

#pragma unroll
    for (int i = 0; i < 4; i++) {
        int tl = w * 4 + i;
        xh[(size_t)(tk0 + tl) * DCH + ch0 + lane] = bfr(sm[lane][tl]);
    }
}

// ---------------------------------------------------------------------------
// plain-bf16 tensor-core GEMM: 3-stage cp.async pipeline + ldmatrix,
// 3 CTAs/SM.  mode 1: gelu(C+bias)->bf16  mode 2: scatter+residual (fp32)
// mode 3: C->bf16
// ---------------------------------------------------------------------------
#define SB   80           // smem row stride bytes (64 data + 16 pad)
#define PLB  10240        // one matrix tile: 128 rows * SB
#define BUFB 20480        // A + B
#define NSTG 3
#define GEMM_SMEM (NSTG * BUFB)

__global__ __launch_bounds__(256, 3) void gemm_tc(
    const ush* __restrict__ Ah, const ush* __restrict__ Bh,
    int M, int N, int K, int mode,
    const float* __restrict__ bias, const float* __restrict__ xres,
    float* __restrict__ outF, ush* __restrict__ oh)
{
    extern __shared__ char smem[];
    const uint32_t sbb = smem_u32(smem);
    const int tid = threadIdx.x;
    const int wid = tid >> 5, lane = tid & 31;
    const int g = lane >> 2, t = lane & 3;
    const int wm = (wid & 3) * 32;
    const int wn = (wid >> 2) * 64;
    const int row0 = blockIdx.y * 128, coln0 = blockIdx.x * 128;

    float acc[2][8][4];
#pragma unroll
    for (int i = 0; i < 2; i++)
#pragma unroll
        for (int j = 0; j < 8; j++)
#pragma unroll
            for (int q = 0; q < 4; q++) acc[i][j][q] = 0.f;

    const int nst = K >> 5;

    const int lr0 = tid >> 2, lc0 = tid & 3;
    const int lr1 = 64 + (tid >> 2);
    int ga0 = row0 + lr0; if (ga0 > M - 1) ga0 = M - 1;
    int ga1 = row0 + lr1; if (ga1 > M - 1) ga1 = M - 1;

#define ISSUE(s, b) do {                                                       \
    int _k0 = (s) << 5;                                                        \
    uint32_t _d0 = sbb + (b) * BUFB + lr0 * SB + lc0 * 16;                     \
    CP_ASYNC16(_d0,       Ah + (size_t)ga0 * K + _k0 + lc0 * 8);               \
    CP_ASYNC16(_d0 + PLB, Bh + (size_t)(coln0 + lr0) * K + _k0 + lc0 * 8);     \
    uint32_t _d1 = sbb + (b) * BUFB + lr1 * SB + lc0 * 16;                     \
    CP_ASYNC16(_d1,       Ah + (size_t)ga1 * K + _k0 + lc0 * 8);               \
    CP_ASYNC16(_d1 + PLB, Bh + (size_t)(coln0 + lr1) * K + _k0 + lc0 * 8);     \
} while (0)

    ISSUE(0, 0); CP_COMMIT();
    ISSUE(1, 1); CP_COMMIT();

    const int arow = (lane & 7) + ((lane >> 3) & 1) * 8;
    const int kh = (lane >> 4) * 16;

    int cur = 0;        // buffer of stage s
    int nxt = 2;        // buffer of stage s+2

    for (int s = 0; s < nst; s++) {
        if (s + 1 < nst) CP_WAIT1();
        else             CP_WAIT0();
        __syncthreads();           // stage s visible; compute of s-1 done (frees buf nxt)
        if (s + 2 < nst) { ISSUE(s + 2, nxt); CP_COMMIT(); }

        const uint32_t pa = sbb + cur * BUFB;
        const uint32_t pb = pa + PLB;
#pragma unroll
        for (int ks = 0; ks < 2; ks++) {
            const uint32_t cb = ks * 32 + kh;
            uint32_t ah[2][4];
#pragma unroll
            for (int mt = 0; mt < 2; mt++) {
                uint32_t ad = pa + (wm + mt * 16 + arow) * SB + cb;
                ldm_x4(ah[mt][0], ah[mt][1], ah[mt][2], ah[mt][3], ad);
            }
            uint32_t bh[8][2];
#pragma unroll
            for (int p = 0; p < 4; p++) {
                uint32_t bd = pb + (wn + p * 16 + arow) * SB + cb;
                ldm_x4(bh[2 * p][0], bh[2 * p + 1][0], bh[2 * p][1], bh[2 * p + 1][1], bd);
            }
#pragma unroll
            for (int mt = 0; mt < 2; mt++)
#pragma unroll
                for (int nt = 0; nt < 8; nt++)
                    mma16816(acc[mt][nt], ah[mt][0], ah[mt][1], ah[mt][2], ah[mt][3],
                             bh[nt][0], bh[nt][1]);
        }
        cur = (cur == 2) ? 0 : cur + 1;
        nxt = (nxt == 2) ? 0 : nxt + 1;
    }
#undef ISSUE

    // ---- epilogue ----
#pragma unroll
    for (int mt = 0; mt < 2; mt++) {
#pragma unroll
        for (int half = 0; half < 2; half++) {
            int r = row0 + wm + mt * 16 + g + half * 8;
            if (r >= M) continue;
#pragma unroll
            for (int nt = 0; nt < 8; nt++) {
                int col = coln0 + wn + nt * 8 + 2 * t;
                float v0 = acc[mt][nt][half * 2 + 0];
                float v1 = acc[mt][nt][half * 2 + 1];
                if (mode == 3) {
                    *(uint32_t*)(oh + (size_t)r * N + col) = pack2bf(v0, v1);
                } else if (mode == 1) {
                    *(uint32_t*)(oh + (size_t)r * N + col) =
                        pack2bf(gelu_exact(v0 + bias[col]),
                                gelu_exact(v1 + bias[col + 1]));
                } else { // mode 2: scatter + residual
                    int bb = r / 10000, rr = r % 10000;
                    int win = rr / 625, tt = rr % 625;
                    int hh2 = (win >> 2) * 25 + tt / 25;
                    int ww = (win & 3) * 25 + tt % 25;
                    int obase = bb * 2560000 + hh2 * 100 + ww;
                    int oi0 = obase + col * 10000;
                    int oi1 = obase + (col + 1) * 10000;
                    outF[oi0] = xres[oi0] + v0 + bias[col];
                    outF[oi1] = xres[oi1] + v1 + bias[col + 1];
                }
            }
        }
    }
}

// ---------------------------------------------------------------------------
// tensor-core windowed attention: bf16, cp.async double-buffered K/V,
// ldmatrix (V via .trans), packed-bf16 exp, row-sum via mma-with-ones.
// grid = (head 8, win 32, qtile 5); CTA 256 thr; 3 CTAs/SM enforced.
// ---------------------------------------------------------------------------
#define SROW 20
#define SBK  80     // row stride bytes for K/V tiles
#define KVB  (64 * SROW)    // one K or V tile in words
#define SL2  0.25503487f    // (1/sqrt(32)) * log2(e)
#define ONES 0x3F803F80u    // bf16x2 {1.0, 1.0}

template<bool LAST>
__device__ __forceinline__ void attn_compute(
    int kb, int t, int arow, int kh,
    uint32_t Kb, uint32_t Vb,
    const float* BL, int add0, int add1,
    const uint32_t qh[2][4], float lacc[4], float oacc[4][4])
{
    // ---- S = Q K^T ----
    float sacc[8][4];
#pragma unroll
    for (int i = 0; i < 8; i++)
#pragma unroll
        for (int j = 0; j < 4; j++) sacc[i][j] = 0.f;

#pragma unroll
    for (int p = 0; p < 4; p++) {
        uint32_t base = Kb + (p * 16 + arow) * SBK + kh;
        uint32_t kA0, kA1, kA2, kA3, kB0, kB1, kB2, kB3;
        ldm_x4(kA0, kA1, kA2, kA3, base);
        ldm_x4(kB0, kB1, kB2, kB3, base + 32);
        mma16816(sacc[2 * p],     qh[0][0], qh[0][1], qh[0][2], qh[0][3], kA0, kA2);
        mma16816(sacc[2 * p + 1], qh[0][0], qh[0][1], qh[0][2], qh[0][3], kA1, kA3);
        mma16816(sacc[2 * p],     qh[1][0], qh[1][1], qh[1][2], qh[1][3], kB0, kB2);
        mma16816(sacc[2 * p + 1], qh[1][0], qh[1][1], qh[1][2], qh[1][3], kB1, kB3);
    }

    // ---- bias + packed bf16 ex2 ----
    const int kbase = kb * 64;
    uint32_t pha[8][2];
#pragma unroll
    for (int nt = 0; nt < 8; nt++) {
        int jl0 = nt * 8 + 2 * t;
        int jg0 = kbase + jl0;
        int jg1 = jg0 + 1;
        int jc0 = LAST ? (jg0 < 624 ? jg0 : 624) : jg0;
        int jc1 = LAST ? (jg1 < 624 ? jg1 : 624) : jg1;
        int sub0 = jc0 + 24 * ((jc0 * 1311) >> 15);
        int sub1 = jc1 + 24 * ((jc1 * 1311) >> 15);
        float t0 = fmaf(sacc[nt][0], SL2, BL[add0 - sub0]);
        float t1 = fmaf(sacc[nt][1], SL2, BL[add0 - sub1]);
        float t2 = fmaf(sacc[nt][2], SL2, BL[add1 - sub0]);
        float t3 = fmaf(sacc[nt][3], SL2, BL[add1 - sub1]);
        if (LAST) {
            if (jg0 >= 625) { t0 = -1e30f; t2 = -1e30f; }
            if (jg1 >= 625) { t1 = -1e30f; t3 = -1e30f; }
        }
        pha[nt][0] = ex2_bf16x2(pack2bf(t0, t1));
        pha[nt][1] = ex2_bf16x2(pack2bf(t2, t3));
    }

    // ---- row sums: lacc += P * ones ----
#pragma unroll
    for (int kc2 = 0; kc2 < 4; kc2++)
        mma16816(lacc, pha[2 * kc2][0], pha[2 * kc2][1],
                 pha[2 * kc2 + 1][0], pha[2 * kc2 + 1][1], ONES, ONES);

    // ---- O += P V ----
#pragma unroll
    for (int p2 = 0; p2 < 2; p2++) {
#pragma unroll
        for (int kc2 = 0; kc2 < 4; kc2++) {
            uint32_t d0, d1, d2, d3;
            ldm_x4t(d0, d1, d2, d3, Vb + (kc2 * 16 + arow) * SBK + p2 * 32 + kh);
            mma16816(oacc[2 * p2],     pha[2 * kc2][0], pha[2 * kc2][1],
                     pha[2 * kc2 + 1][0], pha[2 * kc2 + 1][1], d0, d1);
            mma16816(oacc[2 * p2 + 1], pha[2 * kc2][0], pha[2 * kc2][1],
                     pha[2 * kc2 + 1][0], pha[2 * kc2 + 1][1], d2, d3);
        }
    }
}

__global__ __launch_bounds__(256, 3) void attn_tc(const ush* __restrict__ qh_,
                                                  const float* __restrict__ table,
                                                  ush* __restrict__ oh)
{
    __shared__ uint32_t QHI[128 * SROW];
    __shared__ uint32_t KHI[2 * KVB];
    __shared__ uint32_t VHI[2 * KVB];
    __shared__ float    BL[2401];

    const int head = blockIdx.x;
    const int win  = blockIdx.y;
    const int qt   = blockIdx.z;
    const int tid  = threadIdx.x;
    const int w = tid >> 5, lane = tid & 31;
    const int g = lane >> 2, t = tid & 3;
    const int tok0 = win * 625;
    const int qbase = qt * 128;
    const int arow = (lane & 7) + ((lane >> 3) & 1) * 8;
    const int kh = (lane >> 4) * 16;
    const uint32_t Kb0 = smem_u32(KHI);
    const uint32_t Vb0 = smem_u32(VHI);

    const int lrr = tid >> 2, lcc = tid & 3;
#define KV_ISSUE(kb) do {                                                        \
    int _jg = (kb) * 64 + lrr; if (_jg > 624) _jg = 624;                          \
    size_t _src = (size_t)(tok0 + _jg) * QKVN + head * 32 + lcc * 8;              \
    uint32_t _off = ((kb) & 1) * (KVB * 4) + lrr * SBK + lcc * 16;                \
    CP_ASYNC16(Kb0 + _off, qh_ + _src + 256);                                     \
    CP_ASYNC16(Vb0 + _off, qh_ + _src + 512);                                     \
} while (0)

    KV_ISSUE(0); CP_COMMIT();

    for (int i = tid; i < 2401; i += 256)
        BL[i] = table[i * 8 + head] * 1.4426950408889634f;

#pragma unroll
    for (int it = 0; it < 2; it++) {
        int idx = it * 256 + tid;
        int r = idx >> 2, c = idx & 3;
        int qi = qbase + r;
        uint4 v = make_uint4(0, 0, 0, 0);
        if (qi < 625)
            v = *(const uint4*)(qh_ + (size_t)(tok0 + qi) * QKVN + head * 32 + c * 8);
        *(uint4*)(QHI + r * SROW + c * 4) = v;
    }
    __syncthreads();

    uint32_t qh[2][4];
    {
        int r0 = w * 16 + g;
#pragma unroll
        for (int kc = 0; kc < 2; kc++) {
            qh[kc][0] = QHI[r0 * SROW + kc * 8 + t];
            qh[kc][1] = QHI[(r0 + 8) * SROW + kc * 8 + t];
            qh[kc][2] = QHI[r0 * SROW + kc * 8 + t + 4];
            qh[kc][3] = QHI[(r0 + 8) * SROW + kc * 8 + t + 4];
        }
    }

    const int qi0 = qbase + w * 16 + g;
    const int qi1 = qi0 + 8;
    const int cq0 = qi0 < 625 ? qi0 : 624;
    const int cq1 = qi1 < 625 ? qi1 : 624;
    const int add0 = (cq0 / 25 + 24) * 49 + (cq0 % 25) + 24;
    const int add1 = (cq1 / 25 + 24) * 49 + (cq1 % 25) + 24;

    float lacc[4] = {0.f, 0.f, 0.f, 0.f};
    float oacc[4][4];
#pragma unroll
    for (int i = 0; i < 4; i++)
#pragma unroll
        for (int j = 0; j < 4; j++) oacc[i][j] = 0.f;

#pragma unroll 1
    for (int kb = 0; kb < 9; kb++) {
        CP_WAIT0();
        __syncthreads();
        KV_ISSUE(kb + 1); CP_COMMIT();
        attn_compute<false>(kb, t, arow, kh,
                            Kb0 + (kb & 1) * (KVB * 4),
                            Vb0 + (kb & 1) * (KVB * 4),
                            BL, add0, add1, qh, lacc, oacc);
    }
    CP_WAIT0();
    __syncthreads();
    attn_compute<true>(9, t, arow, kh,
                       Kb0 + (9 & 1) * (KVB * 4),
                       Vb0 + (9 & 1) * (KVB * 4),
                       BL, add0, add1, qh, lacc, oacc);
#undef KV_ISSUE

    float inv0 = 1.f / lacc[0], inv1 = 1.f / lacc[2];

    if (qi0 < 625) {
        size_t o = (size_t)(tok0 + qi0) * DCH + head * 32;
#pragma unroll
        for (int nt2 = 0; nt2 < 4; nt2++) {
            int d = nt2 * 8 + 2 * t;
            *(uint32_t*)(oh + o + d) = pack2bf(oacc[nt2][0] * inv0,
                                               oacc[nt2][1] * inv0);
        }
    }
    if (qi1 < 625) {
        size_t o = (size_t)(tok0 + qi1) * DCH + head * 32;
#pragma unroll
        for (int nt2 = 0; nt2 < 4; nt2++) {
            int d = nt2 * 8 + 2 * t;
            *(uint32_t*)(oh + o + d) = pack2bf(oacc[nt2][2] * inv1,
                                               oacc[nt2][3] * inv1);
        }
    }
}

// ---------------------------------------------------------------------------
// LayerNorm over d=256: one warp per token; bf16 in -> bf16 out
// ---------------------------------------------------------------------------
__global__ __launch_bounds__(256) void ln_kernel(const ush* __restrict__ in,
                                                 ush* __restrict__ oh,
                                                 const float* __restrict__ g,
                                                 const float* __restrict__ b)
{
    int wid = threadIdx.x >> 5, lane = threadIdx.x & 31;
    int t = blockIdx.x * 8 + wid;
    const uint2* p = (const uint2*)(in + (size_t)t * DCH);
    uint2 a = p[lane];
    uint2 c = p[lane + 32];
    float f0 = lo_bf(a.x), f1 = hi_bf(a.x), f2 = lo_bf(a.y), f3 = hi_bf(a.y);
    float f4 = lo_bf(c.x), f5 = hi_bf(c.x), f6 = lo_bf(c.y), f7 = hi_bf(c.y);

    float s  = f0 + f1 + f2 + f3 + f4 + f5 + f6 + f7;
    float ss = f0 * f0 + f1 * f1 + f2 * f2 + f3 * f3
             + f4 * f4 + f5 * f5 + f6 * f6 + f7 * f7;
#pragma unroll
    for (int off = 16; off > 0; off >>= 1) {
        s  += __shfl_xor_sync(0xffffffffu, s, off);
        ss += __shfl_xor_sync(0xffffffffu, ss, off);
    }
    float mean = s * (1.f / 256.f);
    float var  = ss * (1.f / 256.f) - mean * mean;
    float rstd = rsqrtf(var + 1e-5f);

    const float4* g4 = (const float4*)g;
    const float4* b4 = (const float4*)b;
    float4 ga = g4[lane], gb = g4[lane + 32];
    float4 ba = b4[lane], bb = b4[lane + 32];

    uint2 o0, o1;
    o0.x = pack2bf((f0 - mean) * rstd * ga.x + ba.x,
                   (f1 - mean) * rstd * ga.y + ba.y);
    o0.y = pack2bf((f2 - mean) * rstd * ga.z + ba.z,
                   (f3 - mean) * rstd * ga.w + ba.w);
    o1.x = pack2bf((f4 - mean) * rstd * gb.x + bb.x,
                   (f5 - mean) * rstd * gb.y + bb.y);
    o1.y = pack2bf((f6 - mean) * rstd * gb.z + bb.z,
                   (f7 - mean) * rstd * gb.w + bb.w);

    size_t o = (size_t)t * DCH;
    *(uint2*)(oh + o + lane * 4)       = o0;
    *(uint2*)(oh + o + 128 + lane * 4) = o1;
}

// ---------------------------------------------------------------------------
extern "C" void kernel_launch(void* const* d_in, const int* in_sizes, int n_in,
                              void* d_out, int out_size)
{
    const float* x      = (const float*)d_in[0];
    const float* w_qkv  = (const float*)d_in[1];
    const float* w_out  = (const float*)d_in[2];
    const float* table  = (const float*)d_in[3];
    const float* gamma2 = (const float*)d_in[4];
    const float* beta2  = (const float*)d_in[5];
    const float* w1     = (const float*)d_in[6];
    const float* b1     = (const float*)d_in[7];
    const float* w2     = (const float*)d_in[8];
    const float* b2     = (const float*)d_in[9];
    float* out = (float*)d_out;

    ush *xw, *qkv, *att, *ln, *hid, *wv;
    cudaGetSymbolAddress((void**)&xw,  g_xw);
    cudaGetSymbolAddress((void**)&qkv, g_qkv);
    cudaGetSymbolAddress((void**)&att, g_att);
    cudaGetSymbolAddress((void**)&ln,  g_ln);
    cudaGetSymbolAddress((void**)&hid, g_hid);
    cudaGetSymbolAddress((void**)&wv,  g_w);

    cudaFuncSetAttribute(gemm_tc, cudaFuncAttributeMaxDynamicSharedMemorySize, GEMM_SMEM);

    // 0) weights -> bf16 plane
    cvt4_kernel<<<WTOT / 4 / 256, 256>>>(w_qkv, w_out, w1, w2, wv);

    // 1) window partition (transposed, coalesced)
    gather_kernel<<<dim3(625, 8), 256>>>(x, xw);
    // 2) QKV projection -> bf16
    gemm_tc<<<dim3(6, 157), 256, GEMM_SMEM>>>(xw, wv + WQ,
        TOK, QKVN, DCH, 3, nullptr, nullptr, nullptr, qkv);
    // 3) tensor-core windowed attention -> bf16
    attn_tc<<<dim3(8, 32, 5), 256>>>(qkv, table, att);
    // 4) output projection -> bf16 (reuses g_xw)
    gemm_tc<<<dim3(2, 157), 256, GEMM_SMEM>>>(att, wv + WO,
        TOK, DCH, DCH, 3, nullptr, nullptr, nullptr, xw);
    // 5) layernorm (bf16 in) -> bf16
    ln_kernel<<<2500, 256>>>(xw, ln, gamma2, beta2);
    // 6) MLP fc1 + exact GELU -> bf16
    gemm_tc<<<dim3(4, 157), 256, GEMM_SMEM>>>(ln, wv + W1,
        TOK, HID, DCH, 1, b1, nullptr, nullptr, hid);
    // 7) MLP fc2 + bias + un-partition + residual -> d_out (fused scatter)
    gemm_tc<<<dim3(2, 157), 256, GEMM_SMEM>>>(hid, wv + W2,
        TOK, DCH, HID, 2, b2, x, out, nullptr);
}

// round 14
// speedup vs baseline: 1.2654x; 1.2654x over previous
#include <cuda_runtime.h>
#include <cuda_bf16.h>
#include <cstdint>
#include <math.h>

#define TOK 20000      // 2 * 16 windows * 625 tokens
#define DCH 256
#define QKVN 768
#define HID 512

typedef unsigned short ush;

// ---- scratch: plain bf16 planes ----
__device__ ush g_xw  [TOK * DCH];   // gather out / QKV in ; later out-proj out
__device__ ush g_qkv [TOK * QKVN];
__device__ ush g_att [TOK * DCH];   // attn out / out-proj in
__device__ ush g_ln  [TOK * DCH];
__device__ ush g_hid [TOK * HID];
// all four weight matrices concatenated: wqkv | wout | w1 | w2
#define WQ 0
#define WO 196608
#define W1 262144
#define W2 393216
#define WTOT 524288
__device__ ush g_w[WTOT];
// rel-pos bias table transposed per-head and pre-scaled by log2(e)
#define TBL 2401
__device__ float g_tableT[8 * TBL];

// ---------------------------------------------------------------------------
// helpers
// ---------------------------------------------------------------------------
__device__ __forceinline__ uint32_t smem_u32(const void* p) {
    uint32_t a;
    asm("{ .reg .u64 t; cvta.to.shared.u64 t, %1; cvt.u32.u64 %0, t; }" : "=r"(a) : "l"(p));
    return a;
}
#define CP_ASYNC16(dst, src) \
    asm volatile("cp.async.cg.shared.global [%0], [%1], 16;" :: "r"(dst), "l"(src))
#define CP_COMMIT() asm volatile("cp.async.commit_group;")
#define CP_WAIT2()  asm volatile("cp.async.wait_group 2;")
#define CP_WAIT1()  asm volatile("cp.async.wait_group 1;")
#define CP_WAIT0()  asm volatile("cp.async.wait_group 0;")

__device__ __forceinline__ void ldm_x4(uint32_t& d0, uint32_t& d1, uint32_t& d2,
                                       uint32_t& d3, uint32_t addr)
{
    asm volatile("ldmatrix.sync.aligned.m8n8.x4.shared.b16 {%0,%1,%2,%3}, [%4];"
                 : "=r"(d0), "=r"(d1), "=r"(d2), "=r"(d3) : "r"(addr));
}
__device__ __forceinline__ void ldm_x4t(uint32_t& d0, uint32_t& d1, uint32_t& d2,
                                        uint32_t& d3, uint32_t addr)
{
    asm volatile("ldmatrix.sync.aligned.m8n8.x4.trans.shared.b16 {%0,%1,%2,%3}, [%4];"
                 : "=r"(d0), "=r"(d1), "=r"(d2), "=r"(d3) : "r"(addr));
}

__device__ __forceinline__ void mma16816(float c[4], uint32_t a0, uint32_t a1,
                                         uint32_t a2, uint32_t a3,
                                         uint32_t b0, uint32_t b1)
{
    asm volatile(
        "mma.sync.aligned.m16n8k16.row.col.f32.bf16.bf16.f32 "
        "{%0,%1,%2,%3}, {%4,%5,%6,%7}, {%8,%9}, {%0,%1,%2,%3};"
        : "+f"(c[0]), "+f"(c[1]), "+f"(c[2]), "+f"(c[3])
        : "r"(a0), "r"(a1), "r"(a2), "r"(a3), "r"(b0), "r"(b1));
}

__device__ __forceinline__ ush bfr(float f) {
    return __bfloat16_as_ushort(__float2bfloat16_rn(f));
}
// pack 2 floats -> bf16x2 in ONE cvt (lo = first arg)
__device__ __forceinline__ uint32_t pack2bf(float lo, float hi) {
    uint32_t r;
    asm("cvt.rn.bf16x2.f32 %0, %1, %2;" : "=r"(r) : "f"(hi), "f"(lo));
    return r;
}
// packed exp2 on bf16x2
__device__ __forceinline__ uint32_t ex2_bf16x2(uint32_t x) {
    uint32_t r;
    asm("ex2.approx.ftz.bf16x2 %0, %1;" : "=r"(r) : "r"(x));
    return r;
}
__device__ __forceinline__ float lo_bf(uint32_t w) { return __uint_as_float(w << 16); }
__device__ __forceinline__ float hi_bf(uint32_t w) { return __uint_as_float(w & 0xFFFF0000u); }

__device__ __forceinline__ float gelu_exact(float v)
{
    return 0.5f * v * (1.0f + erff(v * 0.70710678118654752f));
}

// ---------------------------------------------------------------------------
// merged prep: weight conversion + rel-bias table transpose (pre-scaled)
// ---------------------------------------------------------------------------
#define TTOT (8 * TBL)
__global__ __launch_bounds__(256) void prep_kernel(
    const float* __restrict__ s0, const float* __restrict__ s1,
    const float* __restrict__ s2, const float* __restrict__ s3,
    const float* __restrict__ table,
    ush* __restrict__ h, float* __restrict__ tT)
{
    int base = (blockIdx.x * blockDim.x + threadIdx.x) * 4;
    if (base < WTOT) {
        const float* src;
        int off;
        if (base < WO)      { src = s0; off = base; }
        else if (base < W1) { src = s1; off = base - WO; }
        else if (base < W2) { src = s2; off = base - W1; }
        else                { src = s3; off = base - W2; }
        float4 v = *(const float4*)(src + off);
        uint2 o;
        o.x = pack2bf(v.x, v.y);
        o.y = pack2bf(v.z, v.w);
        *(uint2*)(h + base) = o;
    } else {
        int ti = base - WTOT;   // over 8*2401 entries of table (row-major 2401x8)
#pragma unroll
        for (int j = 0; j < 4; j++) {
            int idx = ti + j;
            if (idx < TTOT) {
                int pos = idx >> 3, head = idx & 7;
                tT[head * TBL + pos] = table[idx] * 1.4426950408889634f;
            }
        }
    }
}

// ---------------------------------------------------------------------------
// window partition with smem transpose: x (2,256,100,100) -> bf16 (20000,256)
// ---------------------------------------------------------------------------
__global__ __launch_bounds__(256) void gather_kernel(const float* __restrict__ x,
                                                     ush* __restrict__ xh)
{
    __shared__ float sm[32][33];
    const int w = threadIdx.x >> 5, lane = threadIdx.x & 31;
    const int tk0 = blockIdx.x * 32;
    const int ch0 = blockIdx.y * 32;

    {
        int tk = tk0 + lane;
        int bb = tk / 10000, rr = tk % 10000;
        int win = rr / 625, t = rr % 625;
        int hh = (win >> 2) * 25 + t / 25;
        int ww = (win & 3) * 25 + t % 25;
        int base = bb * 2560000 + hh * 100 + ww;
#pragma unroll
        for (int i = 0; i < 4; i++) {
            int ch = ch0 + w * 4 + i;
            sm[w * 4 + i][lane] = x[base + ch * 10000];
        }
    }
    __syncthreads();

#pragma unroll
    for (int i = 0; i < 4; i++) {
        int tl = w * 4 + i;
        xh[(size_t)(tk0 + tl) * DCH + ch0 + lane] = bfr(sm[lane][tl]);
    }
}

// ---------------------------------------------------------------------------
// plain-bf16 tensor-core GEMM: 4-stage cp.async pipeline + ldmatrix (R12 proven).
// mode 1: gelu(C+bias)->bf16  mode 2: scatter+residual (fp32)  mode 3: C->bf16
// ---------------------------------------------------------------------------
#define SB   80           // smem row stride bytes (64 data + 16 pad)
#define PLB  10240        // one matrix tile: 128 rows * SB
#define BUFB 20480        // A + B
#define NSTG 4
#define GEMM_SMEM (NSTG * BUFB)

__global__ __launch_bounds__(256) void gemm_tc(
    const ush* __restrict__ Ah, const ush* __restrict__ Bh,
    int M, int N, int K, int mode,
    const float* __restrict__ bias, const float* __restrict__ xres,
    float* __restrict__ outF, ush* __restrict__ oh)
{
    extern __shared__ char smem[];
    const uint32_t sbb = smem_u32(smem);
    const int tid = threadIdx.x;
    const int wid = tid >> 5, lane = tid & 31;
    const int g = lane >> 2, t = lane & 3;
    const int wm = (wid & 3) * 32;
    const int wn = (wid >> 2) * 64;
    const int row0 = blockIdx.y * 128, coln0 = blockIdx.x * 128;

    float acc[2][8][4];
#pragma unroll
    for (int i = 0; i < 2; i++)
#pragma unroll
        for (int j = 0; j < 8; j++)
#pragma unroll
            for (int q = 0; q < 4; q++) acc[i][j][q] = 0.f;

    const int nst = K >> 5;

    const int lr0 = tid >> 2, lc0 = tid & 3;
    const int lr1 = 64 + (tid >> 2);
    int ga0 = row0 + lr0; if (ga0 > M - 1) ga0 = M - 1;
    int ga1 = row0 + lr1; if (ga1 > M - 1) ga1 = M - 1;

#define ISSUE(s) do {                                                          \
    int _b = (s) & (NSTG - 1);                                                 \
    int _k0 = (s) << 5;                                                        \
    uint32_t _d0 = sbb + _b * BUFB + lr0 * SB + lc0 * 16;                      \
    CP_ASYNC16(_d0,       Ah + (size_t)ga0 * K + _k0 + lc0 * 8);               \
    CP_ASYNC16(_d0 + PLB, Bh + (size_t)(coln0 + lr0) * K + _k0 + lc0 * 8);     \
    uint32_t _d1 = sbb + _b * BUFB + lr1 * SB + lc0 * 16;                      \
    CP_ASYNC16(_d1,       Ah + (size_t)ga1 * K + _k0 + lc0 * 8);               \
    CP_ASYNC16(_d1 + PLB, Bh + (size_t)(coln0 + lr1) * K + _k0 + lc0 * 8);     \
} while (0)

    ISSUE(0); CP_COMMIT();
    ISSUE(1); CP_COMMIT();
    ISSUE(2); CP_COMMIT();

    const int arow = (lane & 7) + ((lane >> 3) & 1) * 8;
    const int kh = (lane >> 4) * 16;

    for (int s = 0; s < nst; s++) {
        if (s + 3 <= nst)      CP_WAIT2();
        else if (s + 2 == nst) CP_WAIT1();
        else                   CP_WAIT0();
        __syncthreads();
        if (s + 3 < nst) { ISSUE(s + 3); CP_COMMIT(); }

        const uint32_t pa = sbb + (s & (NSTG - 1)) * BUFB;
        const uint32_t pb = pa + PLB;
#pragma unroll
        for (int ks = 0; ks < 2; ks++) {
            const uint32_t cb = ks * 32 + kh;
            uint32_t ah[2][4];
#pragma unroll
            for (int mt = 0; mt < 2; mt++) {
                uint32_t ad = pa + (wm + mt * 16 + arow) * SB + cb;
                ldm_x4(ah[mt][0], ah[mt][1], ah[mt][2], ah[mt][3], ad);
            }
            uint32_t bh[8][2];
#pragma unroll
            for (int p = 0; p < 4; p++) {
                uint32_t bd = pb + (wn + p * 16 + arow) * SB + cb;
                ldm_x4(bh[2 * p][0], bh[2 * p + 1][0], bh[2 * p][1], bh[2 * p + 1][1], bd);
            }
#pragma unroll
            for (int mt = 0; mt < 2; mt++)
#pragma unroll
                for (int nt = 0; nt < 8; nt++)
                    mma16816(acc[mt][nt], ah[mt][0], ah[mt][1], ah[mt][2], ah[mt][3],
                             bh[nt][0], bh[nt][1]);
        }
    }
#undef ISSUE

    // ---- epilogue ----
#pragma unroll
    for (int mt = 0; mt < 2; mt++) {
#pragma unroll
        for (int half = 0; half < 2; half++) {
            int r = row0 + wm + mt * 16 + g + half * 8;
            if (r >= M) continue;
#pragma unroll
            for (int nt = 0; nt < 8; nt++) {
                int col = coln0 + wn + nt * 8 + 2 * t;
                float v0 = acc[mt][nt][half * 2 + 0];
                float v1 = acc[mt][nt][half * 2 + 1];
                if (mode == 3) {
                    *(uint32_t*)(oh + (size_t)r * N + col) = pack2bf(v0, v1);
                } else if (mode == 1) {
                    *(uint32_t*)(oh + (size_t)r * N + col) =
                        pack2bf(gelu_exact(v0 + bias[col]),
                                gelu_exact(v1 + bias[col + 1]));
                } else { // mode 2: scatter + residual
                    int bb = r / 10000, rr = r % 10000;
                    int win = rr / 625, tt = rr % 625;
                    int hh2 = (win >> 2) * 25 + tt / 25;
                    int ww = (win & 3) * 25 + tt % 25;
                    int obase = bb * 2560000 + hh2 * 100 + ww;
                    int oi0 = obase + col * 10000;
                    int oi1 = obase + (col + 1) * 10000;
                    outF[oi0] = xres[oi0] + v0 + bias[col];
                    outF[oi1] = xres[oi1] + v1 + bias[col + 1];
                }
            }
        }
    }
}

// ---------------------------------------------------------------------------
// tensor-core windowed attention: bf16, cp.async double-buffered K/V,
// ldmatrix (V via .trans), packed-bf16 exp, row-sum via mma-with-ones.
// grid = (head 8, win 32, qtile 5); CTA 256 thr; 3 CTAs/SM enforced.
// ---------------------------------------------------------------------------
#define SROW 20
#define SBK  80     // row stride bytes for K/V tiles
#define KVB  (64 * SROW)    // one K or V tile in words
#define SL2  0.25503487f    // (1/sqrt(32)) * log2(e)
#define ONES 0x3F803F80u    // bf16x2 {1.0, 1.0}

template<bool LAST>
__device__ __forceinline__ void attn_compute(
    int kb, int t, int arow, int kh,
    uint32_t Kb, uint32_t Vb,
    const float* BL, int add0, int add1,
    const uint32_t qh[2][4], float lacc[4], float oacc[4][4])
{
    // ---- S = Q K^T ----
    float sacc[8][4];
#pragma unroll
    for (int i = 0; i < 8; i++)
#pragma unroll
        for (int j = 0; j < 4; j++) sacc[i][j] = 0.f;

#pragma unroll
    for (int p = 0; p < 4; p++) {
        uint32_t base = Kb + (p * 16 + arow) * SBK + kh;
        uint32_t kA0, kA1, kA2, kA3, kB0, kB1, kB2, kB3;
        ldm_x4(kA0, kA1, kA2, kA3, base);
        ldm_x4(kB0, kB1, kB2, kB3, base + 32);
        mma16816(sacc[2 * p],     qh[0][0], qh[0][1], qh[0][2], qh[0][3], kA0, kA2);
        mma16816(sacc[2 * p + 1], qh[0][0], qh[0][1], qh[0][2], qh[0][3], kA1, kA3);
        mma16816(sacc[2 * p],     qh[1][0], qh[1][1], qh[1][2], qh[1][3], kB0, kB2);
        mma16816(sacc[2 * p + 1], qh[1][0], qh[1][1], qh[1][2], qh[1][3], kB1, kB3);
    }

    // ---- bias + packed bf16 ex2 ----
    const int kbase = kb * 64;
    uint32_t pha[8][2];
#pragma unroll
    for (int nt = 0; nt < 8; nt++) {
        int jl0 = nt * 8 + 2 * t;
        int jg0 = kbase + jl0;
        int jg1 = jg0 + 1;
        int jc0 = LAST ? (jg0 < 624 ? jg0 : 624) : jg0;
        int jc1 = LAST ? (jg1 < 624 ? jg1 : 624) : jg1;
        int sub0 = jc0 + 24 * ((jc0 * 1311) >> 15);
        int sub1 = jc1 + 24 * ((jc1 * 1311) >> 15);
        float t0 = fmaf(sacc[nt][0], SL2, BL[add0 - sub0]);
        float t1 = fmaf(sacc[nt][1], SL2, BL[add0 - sub1]);
        float t2 = fmaf(sacc[nt][2], SL2, BL[add1 - sub0]);
        float t3 = fmaf(sacc[nt][3], SL2, BL[add1 - sub1]);
        if (LAST) {
            if (jg0 >= 625) { t0 = -1e30f; t2 = -1e30f; }
            if (jg1 >= 625) { t1 = -1e30f; t3 = -1e30f; }
        }
        pha[nt][0] = ex2_bf16x2(pack2bf(t0, t1));
        pha[nt][1] = ex2_bf16x2(pack2bf(t2, t3));
    }

    // ---- row sums: lacc += P * ones ----
#pragma unroll
    for (int kc2 = 0; kc2 < 4; kc2++)
        mma16816(lacc, pha[2 * kc2][0], pha[2 * kc2][1],
                 pha[2 * kc2 + 1][0], pha[2 * kc2 + 1][1], ONES, ONES);

    // ---- O += P V ----
#pragma unroll
    for (int p2 = 0; p2 < 2; p2++) {
#pragma unroll
        for (int kc2 = 0; kc2 < 4; kc2++) {
            uint32_t d0, d1, d2, d3;
            ldm_x4t(d0, d1, d2, d3, Vb + (kc2 * 16 + arow) * SBK + p2 * 32 + kh);
            mma16816(oacc[2 * p2],     pha[2 * kc2][0], pha[2 * kc2][1],
                     pha[2 * kc2 + 1][0], pha[2 * kc2 + 1][1], d0, d1);
            mma16816(oacc[2 * p2 + 1], pha[2 * kc2][0], pha[2 * kc2][1],
                     pha[2 * kc2 + 1][0], pha[2 * kc2 + 1][1], d2, d3);
        }
    }
}

__global__ __launch_bounds__(256, 3) void attn_tc(const ush* __restrict__ qh_,
                                                  const float* __restrict__ tT,
                                                  ush* __restrict__ oh)
{
    __shared__ uint32_t QHI[128 * SROW];
    __shared__ uint32_t KHI[2 * KVB];
    __shared__ uint32_t VHI[2 * KVB];
    __shared__ float    BL[TBL];

    const int head = blockIdx.x;
    const int win  = blockIdx.y;
    const int qt   = blockIdx.z;
    const int tid  = threadIdx.x;
    const int w = tid >> 5, lane = tid & 31;
    const int g = lane >> 2, t = tid & 3;
    const int tok0 = win * 625;
    const int qbase = qt * 128;
    const int arow = (lane & 7) + ((lane >> 3) & 1) * 8;
    const int kh = (lane >> 4) * 16;
    const uint32_t Kb0 = smem_u32(KHI);
    const uint32_t Vb0 = smem_u32(VHI);

    const int lrr = tid >> 2, lcc = tid & 3;
#define KV_ISSUE(kb) do {                                                        \
    int _jg = (kb) * 64 + lrr; if (_jg > 624) _jg = 624;                          \
    size_t _src = (size_t)(tok0 + _jg) * QKVN + head * 32 + lcc * 8;              \
    uint32_t _off = ((kb) & 1) * (KVB * 4) + lrr * SBK + lcc * 16;                \
    CP_ASYNC16(Kb0 + _off, qh_ + _src + 256);                                     \
    CP_ASYNC16(Vb0 + _off, qh_ + _src + 512);                                     \
} while (0)

    KV_ISSUE(0); CP_COMMIT();

    // coalesced: table already transposed + pre-scaled by log2(e)
    const float* tH = tT + head * TBL;
    for (int i = tid; i < TBL; i += 256) BL[i] = tH[i];

#pragma unroll
    for (int it = 0; it < 2; it++) {
        int idx = it * 256 + tid;
        int r = idx >> 2, c = idx & 3;
        int qi = qbase + r;
        uint4 v = make_uint4(0, 0, 0, 0);
        if (qi < 625)
            v = *(const uint4*)(qh_ + (size_t)(tok0 + qi) * QKVN + head * 32 + c * 8);
        *(uint4*)(QHI + r * SROW + c * 4) = v;
    }
    __syncthreads();

    uint32_t qh[2][4];
    {
        int r0 = w * 16 + g;
#pragma unroll
        for (int kc = 0; kc < 2; kc++) {
            qh[kc][0] = QHI[r0 * SROW + kc * 8 + t];
            qh[kc][1] = QHI[(r0 + 8) * SROW + kc * 8 + t];
            qh[kc][2] = QHI[r0 * SROW + kc * 8 + t + 4];
            qh[kc][3] = QHI[(r0 + 8) * SROW + kc * 8 + t + 4];
        }
    }

    const int qi0 = qbase + w * 16 + g;
    const int qi1 = qi0 + 8;
    const int cq0 = qi0 < 625 ? qi0 : 624;
    const int cq1 = qi1 < 625 ? qi1 : 624;
    const int add0 = (cq0 / 25 + 24) * 49 + (cq0 % 25) + 24;
    const int add1 = (cq1 / 25 + 24) * 49 + (cq1 % 25) + 24;

    float lacc[4] = {0.f, 0.f, 0.f, 0.f};
    float oacc[4][4];
#pragma unroll
    for (int i = 0; i < 4; i++)
#pragma unroll
        for (int j = 0; j < 4; j++) oacc[i][j] = 0.f;

#pragma unroll 1
    for (int kb = 0; kb < 9; kb++) {
        CP_WAIT0();
        __syncthreads();
        KV_ISSUE(kb + 1); CP_COMMIT();
        attn_compute<false>(kb, t, arow, kh,
                            Kb0 + (kb & 1) * (KVB * 4),
                            Vb0 + (kb & 1) * (KVB * 4),
                            BL, add0, add1, qh, lacc, oacc);
    }
    CP_WAIT0();
    __syncthreads();
    attn_compute<true>(9, t, arow, kh,
                       Kb0 + (9 & 1) * (KVB * 4),
                       Vb0 + (9 & 1) * (KVB * 4),
                       BL, add0, add1, qh, lacc, oacc);
#undef KV_ISSUE

    float inv0 = 1.f / lacc[0], inv1 = 1.f / lacc[2];

    if (qi0 < 625) {
        size_t o = (size_t)(tok0 + qi0) * DCH + head * 32;
#pragma unroll
        for (int nt2 = 0; nt2 < 4; nt2++) {
            int d = nt2 * 8 + 2 * t;
            *(uint32_t*)(oh + o + d) = pack2bf(oacc[nt2][0] * inv0,
                                               oacc[nt2][1] * inv0);
        }
    }
    if (qi1 < 625) {
        size_t o = (size_t)(tok0 + qi1) * DCH + head * 32;
#pragma unroll
        for (int nt2 = 0; nt2 < 4; nt2++) {
            int d = nt2 * 8 + 2 * t;
            *(uint32_t*)(oh + o + d) = pack2bf(oacc[nt2][2] * inv1,
                                               oacc[nt2][3] * inv1);
        }
    }
}

// ---------------------------------------------------------------------------
// LayerNorm over d=256: one warp per token; bf16 in -> bf16 out
// ---------------------------------------------------------------------------
__global__ __launch_bounds__(256) void ln_kernel(const ush* __restrict__ in,
                                                 ush* __restrict__ oh,
                                                 const float* __restrict__ g,
                                                 const float* __restrict__ b)
{
    int wid = threadIdx.x >> 5, lane = threadIdx.x & 31;
    int t = blockIdx.x * 8 + wid;
    const uint2* p = (const uint2*)(in + (size_t)t * DCH);
    uint2 a = p[lane];
    uint2 c = p[lane + 32];
    float f0 = lo_bf(a.x), f1 = hi_bf(a.x), f2 = lo_bf(a.y), f3 = hi_bf(a.y);
    float f4 = lo_bf(c.x), f5 = hi_bf(c.x), f6 = lo_bf(c.y), f7 = hi_bf(c.y);

    float s  = f0 + f1 + f2 + f3 + f4 + f5 + f6 + f7;
    float ss = f0 * f0 + f1 * f1 + f2 * f2 + f3 * f3
             + f4 * f4 + f5 * f5 + f6 * f6 + f7 * f7;
#pragma unroll
    for (int off = 16; off > 0; off >>= 1) {
        s  += __shfl_xor_sync(0xffffffffu, s, off);
        ss += __shfl_xor_sync(0xffffffffu, ss, off);
    }
    float mean = s * (1.f / 256.f);
    float var  = ss * (1.f / 256.f) - mean * mean;
    float rstd = rsqrtf(var + 1e-5f);

    const float4* g4 = (const float4*)g;
    const float4* b4 = (const float4*)b;
    float4 ga = g4[lane], gb = g4[lane + 32];
    float4 ba = b4[lane], bb = b4[lane + 32];

    uint2 o0, o1;
    o0.x = pack2bf((f0 - mean) * rstd * ga.x + ba.x,
                   (f1 - mean) * rstd * ga.y + ba.y);
    o0.y = pack2bf((f2 - mean) * rstd * ga.z + ba.z,
                   (f3 - mean) * rstd * ga.w + ba.w);
    o1.x = pack2bf((f4 - mean) * rstd * gb.x + bb.x,
                   (f5 - mean) * rstd * gb.y + bb.y);
    o1.y = pack2bf((f6 - mean) * rstd * gb.z + bb.z,
                   (f7 - mean) * rstd * gb.w + bb.w);

    size_t o = (size_t)t * DCH;
    *(uint2*)(oh + o + lane * 4)       = o0;
    *(uint2*)(oh + o + 128 + lane * 4) = o1;
}

// ---------------------------------------------------------------------------
extern "C" void kernel_launch(void* const* d_in, const int* in_sizes, int n_in,
                              void* d_out, int out_size)
{
    const float* x      = (const float*)d_in[0];
    const float* w_qkv  = (const float*)d_in[1];
    const float* w_out  = (const float*)d_in[2];
    const float* table  = (const float*)d_in[3];
    const float* gamma2 = (const float*)d_in[4];
    const float* beta2  = (const float*)d_in[5];
    const float* w1     = (const float*)d_in[6];
    const float* b1     = (const float*)d_in[7];
    const float* w2     = (const float*)d_in[8];
    const float* b2     = (const float*)d_in[9];
    float* out = (float*)d_out;

    ush *xw, *qkv, *att, *ln, *hid, *wv;
    float *tT;
    cudaGetSymbolAddress((void**)&xw,  g_xw);
    cudaGetSymbolAddress((void**)&qkv, g_qkv);
    cudaGetSymbolAddress((void**)&att, g_att);
    cudaGetSymbolAddress((void**)&ln,  g_ln);
    cudaGetSymbolAddress((void**)&hid, g_hid);
    cudaGetSymbolAddress((void**)&wv,  g_w);
    cudaGetSymbolAddress((void**)&tT,  g_tableT);

    cudaFuncSetAttribute(gemm_tc, cudaFuncAttributeMaxDynamicSharedMemorySize, GEMM_SMEM);

    // 0) weights -> bf16 plane + table transpose (one launch)
    prep_kernel<<<(WTOT + TTOT + 1023) / 1024, 256>>>(w_qkv, w_out, w1, w2,
                                                      table, wv, tT);

    // 1) window partition (transposed, coalesced)
    gather_kernel<<<dim3(625, 8), 256>>>(x, xw);
    // 2) QKV projection -> bf16
    gemm_tc<<<dim3(6, 157), 256, GEMM_SMEM>>>(xw, wv + WQ,
        TOK, QKVN, DCH, 3, nullptr, nullptr, nullptr, qkv);
    // 3) tensor-core windowed attention -> bf16
    attn_tc<<<dim3(8, 32, 5), 256>>>(qkv, tT, att);
    // 4) output projection -> bf16 (reuses g_xw)
    gemm_tc<<<dim3(2, 157), 256, GEMM_SMEM>>>(att, wv + WO,
        TOK, DCH, DCH, 3, nullptr, nullptr, nullptr, xw);
    // 5) layernorm (bf16 in) -> bf16
    ln_kernel<<<2500, 256>>>(xw, ln, gamma2, beta2);
    // 6) MLP fc1 + exact GELU -> bf16
    gemm_tc<<<dim3(4, 157), 256, GEMM_SMEM>>>(ln, wv + W1,
        TOK, HID, DCH, 1, b1, nullptr, nullptr, hid);
    // 7) MLP fc2 + bias + un-partition + residual -> d_out (fused scatter)
    gemm_tc<<<dim3(2, 157), 256, GEMM_SMEM>>>(hid, wv + W2,
        TOK, DCH, HID, 2, b2, x, out, nullptr);
}

// round 15
// speedup vs baseline: 1.3027x; 1.0295x over previous
#include <cuda_runtime.h>
#include <cuda_bf16.h>
#include <cstdint>
#include <math.h>

#define TOK 20000      // 2 * 16 windows * 625 tokens
#define DCH 256
#define QKVN 768
#define HID 512

typedef unsigned short ush;

// ---- scratch: plain bf16 planes ----
__device__ ush g_xw  [TOK * DCH];   // gather out / QKV in ; later out-proj out
__device__ ush g_qkv [TOK * QKVN];
__device__ ush g_att [TOK * DCH];   // attn out / out-proj in
__device__ ush g_ln  [TOK * DCH];
__device__ ush g_hid [TOK * HID];
// all four weight matrices concatenated: wqkv | wout | w1 | w2
#define WQ 0
#define WO 196608
#define W1 262144
#define W2 393216
#define WTOT 524288
__device__ ush g_w[WTOT];
// rel-pos bias table transposed per-head and pre-scaled by log2(e)
#define TBL 2401
__device__ float g_tableT[8 * TBL];

// ---------------------------------------------------------------------------
// helpers
// ---------------------------------------------------------------------------
__device__ __forceinline__ uint32_t smem_u32(const void* p) {
    uint32_t a;
    asm("{ .reg .u64 t; cvta.to.shared.u64 t, %1; cvt.u32.u64 %0, t; }" : "=r"(a) : "l"(p));
    return a;
}
#define CP_ASYNC16(dst, src) \
    asm volatile("cp.async.cg.shared.global [%0], [%1], 16;" :: "r"(dst), "l"(src))
#define CP_COMMIT() asm volatile("cp.async.commit_group;")
#define CP_WAIT2()  asm volatile("cp.async.wait_group 2;")
#define CP_WAIT1()  asm volatile("cp.async.wait_group 1;")
#define CP_WAIT0()  asm volatile("cp.async.wait_group 0;")

__device__ __forceinline__ void ldm_x4(uint32_t& d0, uint32_t& d1, uint32_t& d2,
                                       uint32_t& d3, uint32_t addr)
{
    asm volatile("ldmatrix.sync.aligned.m8n8.x4.shared.b16 {%0,%1,%2,%3}, [%4];"
                 : "=r"(d0), "=r"(d1), "=r"(d2), "=r"(d3) : "r"(addr));
}
__device__ __forceinline__ void ldm_x4t(uint32_t& d0, uint32_t& d1, uint32_t& d2,
                                        uint32_t& d3, uint32_t addr)
{
    asm volatile("ldmatrix.sync.aligned.m8n8.x4.trans.shared.b16 {%0,%1,%2,%3}, [%4];"
                 : "=r"(d0), "=r"(d1), "=r"(d2), "=r"(d3) : "r"(addr));
}

__device__ __forceinline__ void mma16816(float c[4], uint32_t a0, uint32_t a1,
                                         uint32_t a2, uint32_t a3,
                                         uint32_t b0, uint32_t b1)
{
    asm volatile(
        "mma.sync.aligned.m16n8k16.row.col.f32.bf16.bf16.f32 "
        "{%0,%1,%2,%3}, {%4,%5,%6,%7}, {%8,%9}, {%0,%1,%2,%3};"
        : "+f"(c[0]), "+f"(c[1]), "+f"(c[2]), "+f"(c[3])
        : "r"(a0), "r"(a1), "r"(a2), "r"(a3), "r"(b0), "r"(b1));
}

__device__ __forceinline__ ush bfr(float f) {
    return __bfloat16_as_ushort(__float2bfloat16_rn(f));
}
// pack 2 floats -> bf16x2 in ONE cvt (lo = first arg)
__device__ __forceinline__ uint32_t pack2bf(float lo, float hi) {
    uint32_t r;
    asm("cvt.rn.bf16x2.f32 %0, %1, %2;" : "=r"(r) : "f"(hi), "f"(lo));
    return r;
}
// packed exp2 on bf16x2
__device__ __forceinline__ uint32_t ex2_bf16x2(uint32_t x) {
    uint32_t r;
    asm("ex2.approx.ftz.bf16x2 %0, %1;" : "=r"(r) : "r"(x));
    return r;
}
__device__ __forceinline__ float lo_bf(uint32_t w) { return __uint_as_float(w << 16); }
__device__ __forceinline__ float hi_bf(uint32_t w) { return __uint_as_float(w & 0xFFFF0000u); }

__device__ __forceinline__ float gelu_exact(float v)
{
    return 0.5f * v * (1.0f + erff(v * 0.70710678118654752f));
}

// ---------------------------------------------------------------------------
// merged prep: weight conversion + rel-bias table transpose (pre-scaled)
// ---------------------------------------------------------------------------
#define TTOT (8 * TBL)
__global__ __launch_bounds__(256) void prep_kernel(
    const float* __restrict__ s0, const float* __restrict__ s1,
    const float* __restrict__ s2, const float* __restrict__ s3,
    const float* __restrict__ table,
    ush* __restrict__ h, float* __restrict__ tT)
{
    int base = (blockIdx.x * blockDim.x + threadIdx.x) * 4;
    if (base < WTOT) {
        const float* src;
        int off;
        if (base < WO)      { src = s0; off = base; }
        else if (base < W1) { src = s1; off = base - WO; }
        else if (base < W2) { src = s2; off = base - W1; }
        else                { src = s3; off = base - W2; }
        float4 v = *(const float4*)(src + off);
        uint2 o;
        o.x = pack2bf(v.x, v.y);
        o.y = pack2bf(v.z, v.w);
        *(uint2*)(h + base) = o;
    } else {
        int ti = base - WTOT;   // over 8*2401 entries of table (row-major 2401x8)
#pragma unroll
        for (int j = 0; j < 4; j++) {
            int idx = ti + j;
            if (idx < TTOT) {
                int pos = idx >> 3, head = idx & 7;
                tT[head * TBL + pos] = table[idx] * 1.4426950408889634f;
            }
        }
    }
}

// ---------------------------------------------------------------------------
// window partition with smem transpose: x (2,256,100,100) -> bf16 (20000,256)
// ---------------------------------------------------------------------------
__global__ __launch_bounds__(256) void gather_kernel(const float* __restrict__ x,
                                                     ush* __restrict__ xh)
{
    __shared__ float sm[32][33];
    const int w = threadIdx.x >> 5, lane = threadIdx.x & 31;
    const int tk0 = blockIdx.x * 32;
    const int ch0 = blockIdx.y * 32;

    {
        int tk = tk0 + lane;
        int bb = tk / 10000, rr = tk % 10000;
        int win = rr / 625, t = rr % 625;
        int hh = (win >> 2) * 25 + t / 25;
        int ww = (win & 3) * 25 + t % 25;
        int base = bb * 2560000 + hh * 100 + ww;
#pragma unroll
        for (int i = 0; i < 4; i++) {
            int ch = ch0 + w * 4 + i;
            sm[w * 4 + i][lane] = x[base + ch * 10000];
        }
    }
    __syncthreads();

#pragma unroll
    for (int i = 0; i < 4; i++) {
        int tl = w * 4 + i;
        xh[(size_t)(tk0 + tl) * DCH + ch0 + lane] = bfr(sm[lane][tl]);
    }
}

// ---------------------------------------------------------------------------
// plain-bf16 tensor-core GEMM: tile 128x64, warp 32x32, 3 CTAs/SM,
// 4-stage cp.async pipeline + ldmatrix.
// mode 1: gelu(C+bias)->bf16  mode 2: scatter+residual (fp32)  mode 3: C->bf16
// ---------------------------------------------------------------------------
#define SB    80          // smem row stride bytes (64 data + 16 pad)
#define PLBA  10240       // A tile: 128 rows * SB
#define PLBB  5120        // B tile: 64 rows * SB
#define BUFB  15360       // A + B
#define NSTG  4
#define GEMM_SMEM (NSTG * BUFB)

__global__ __launch_bounds__(256, 3) void gemm_tc(
    const ush* __restrict__ Ah, const ush* __restrict__ Bh,
    int M, int N, int K, int mode,
    const float* __restrict__ bias, const float* __restrict__ xres,
    float* __restrict__ outF, ush* __restrict__ oh)
{
    extern __shared__ char smem[];
    const uint32_t sbb = smem_u32(smem);
    const int tid = threadIdx.x;
    const int wid = tid >> 5, lane = tid & 31;
    const int g = lane >> 2, t = lane & 3;
    const int wm = (wid & 3) * 32;
    const int wn = (wid >> 2) * 32;
    const int row0 = blockIdx.y * 128, coln0 = blockIdx.x * 64;

    float acc[2][4][4];
#pragma unroll
    for (int i = 0; i < 2; i++)
#pragma unroll
        for (int j = 0; j < 4; j++)
#pragma unroll
            for (int q = 0; q < 4; q++) acc[i][j][q] = 0.f;

    const int nst = K >> 5;

    // A loader: 512 16B-chunks, 2 per thread; B loader: 256 chunks, 1 per thread
    const int lr0 = tid >> 2, lc0 = tid & 3;
    const int lr1 = 64 + (tid >> 2);
    int ga0 = row0 + lr0; if (ga0 > M - 1) ga0 = M - 1;
    int ga1 = row0 + lr1; if (ga1 > M - 1) ga1 = M - 1;
    const int gb0 = coln0 + lr0;   // B row (0..63 local)

#define ISSUE(s) do {                                                          \
    int _b = (s) & (NSTG - 1);                                                 \
    int _k0 = (s) << 5;                                                        \
    uint32_t _d0 = sbb + _b * BUFB + lr0 * SB + lc0 * 16;                      \
    CP_ASYNC16(_d0,        Ah + (size_t)ga0 * K + _k0 + lc0 * 8);              \
    CP_ASYNC16(_d0 + PLBA, Bh + (size_t)gb0 * K + _k0 + lc0 * 8);              \
    uint32_t _d1 = sbb + _b * BUFB + lr1 * SB + lc0 * 16;                      \
    CP_ASYNC16(_d1,        Ah + (size_t)ga1 * K + _k0 + lc0 * 8);              \
} while (0)

    ISSUE(0); CP_COMMIT();
    ISSUE(1); CP_COMMIT();
    ISSUE(2); CP_COMMIT();

    const int arow = (lane & 7) + ((lane >> 3) & 1) * 8;
    const int kh = (lane >> 4) * 16;

    for (int s = 0; s < nst; s++) {
        if (s + 3 <= nst)      CP_WAIT2();
        else if (s + 2 == nst) CP_WAIT1();
        else                   CP_WAIT0();
        __syncthreads();
        if (s + 3 < nst) { ISSUE(s + 3); CP_COMMIT(); }

        const uint32_t pa = sbb + (s & (NSTG - 1)) * BUFB;
        const uint32_t pb = pa + PLBA;
#pragma unroll
        for (int ks = 0; ks < 2; ks++) {
            const uint32_t cb = ks * 32 + kh;
            uint32_t ah[2][4];
#pragma unroll
            for (int mt = 0; mt < 2; mt++) {
                uint32_t ad = pa + (wm + mt * 16 + arow) * SB + cb;
                ldm_x4(ah[mt][0], ah[mt][1], ah[mt][2], ah[mt][3], ad);
            }
            uint32_t bh[4][2];
#pragma unroll
            for (int p = 0; p < 2; p++) {
                uint32_t bd = pb + (wn + p * 16 + arow) * SB + cb;
                ldm_x4(bh[2 * p][0], bh[2 * p + 1][0], bh[2 * p][1], bh[2 * p + 1][1], bd);
            }
#pragma unroll
            for (int mt = 0; mt < 2; mt++)
#pragma unroll
                for (int nt = 0; nt < 4; nt++)
                    mma16816(acc[mt][nt], ah[mt][0], ah[mt][1], ah[mt][2], ah[mt][3],
                             bh[nt][0], bh[nt][1]);
        }
    }
#undef ISSUE

    // ---- epilogue ----
#pragma unroll
    for (int mt = 0; mt < 2; mt++) {
#pragma unroll
        for (int half = 0; half < 2; half++) {
            int r = row0 + wm + mt * 16 + g + half * 8;
            if (r >= M) continue;
#pragma unroll
            for (int nt = 0; nt < 4; nt++) {
                int col = coln0 + wn + nt * 8 + 2 * t;
                float v0 = acc[mt][nt][half * 2 + 0];
                float v1 = acc[mt][nt][half * 2 + 1];
                if (mode == 3) {
                    *(uint32_t*)(oh + (size_t)r * N + col) = pack2bf(v0, v1);
                } else if (mode == 1) {
                    *(uint32_t*)(oh + (size_t)r * N + col) =
                        pack2bf(gelu_exact(v0 + bias[col]),
                                gelu_exact(v1 + bias[col + 1]));
                } else { // mode 2: scatter + residual
                    int bb = r / 10000, rr = r % 10000;
                    int win = rr / 625, tt = rr % 625;
                    int hh2 = (win >> 2) * 25 + tt / 25;
                    int ww = (win & 3) * 25 + tt % 25;
                    int obase = bb * 2560000 + hh2 * 100 + ww;
                    int oi0 = obase + col * 10000;
                    int oi1 = obase + (col + 1) * 10000;
                    outF[oi0] = xres[oi0] + v0 + bias[col];
                    outF[oi1] = xres[oi1] + v1 + bias[col + 1];
                }
            }
        }
    }
}

// ---------------------------------------------------------------------------
// tensor-core windowed attention: bf16, cp.async double-buffered K/V,
// ldmatrix (V via .trans), packed-bf16 exp, row-sum via mma-with-ones.
// grid = (head 8, win 32, qtile 5); CTA 256 thr; 3 CTAs/SM enforced.
// ---------------------------------------------------------------------------
#define SROW 20
#define SBK  80     // row stride bytes for K/V tiles
#define KVB  (64 * SROW)    // one K or V tile in words
#define SL2  0.25503487f    // (1/sqrt(32)) * log2(e)
#define ONES 0x3F803F80u    // bf16x2 {1.0, 1.0}

template<bool LAST>
__device__ __forceinline__ void attn_compute(
    int kb, int t, int arow, int kh,
    uint32_t Kb, uint32_t Vb,
    const float* BL, int add0, int add1,
    const uint32_t qh[2][4], float lacc[4], float oacc[4][4])
{
    // ---- S = Q K^T ----
    float sacc[8][4];
#pragma unroll
    for (int i = 0; i < 8; i++)
#pragma unroll
        for (int j = 0; j < 4; j++) sacc[i][j] = 0.f;

#pragma unroll
    for (int p = 0; p < 4; p++) {
        uint32_t base = Kb + (p * 16 + arow) * SBK + kh;
        uint32_t kA0, kA1, kA2, kA3, kB0, kB1, kB2, kB3;
        ldm_x4(kA0, kA1, kA2, kA3, base);
        ldm_x4(kB0, kB1, kB2, kB3, base + 32);
        mma16816(sacc[2 * p],     qh[0][0], qh[0][1], qh[0][2], qh[0][3], kA0, kA2);
        mma16816(sacc[2 * p + 1], qh[0][0], qh[0][1], qh[0][2], qh[0][3], kA1, kA3);
        mma16816(sacc[2 * p],     qh[1][0], qh[1][1], qh[1][2], qh[1][3], kB0, kB2);
        mma16816(sacc[2 * p + 1], qh[1][0], qh[1][1], qh[1][2], qh[1][3], kB1, kB3);
    }

    // ---- bias + packed bf16 ex2 ----
    const int kbase = kb * 64;
    uint32_t pha[8][2];
#pragma unroll
    for (int nt = 0; nt < 8; nt++) {
        int jl0 = nt * 8 + 2 * t;
        int jg0 = kbase + jl0;
        int jg1 = jg0 + 1;
        int jc0 = LAST ? (jg0 < 624 ? jg0 : 624) : jg0;
        int jc1 = LAST ? (jg1 < 624 ? jg1 : 624) : jg1;
        int sub0 = jc0 + 24 * ((jc0 * 1311) >> 15);
        int sub1 = jc1 + 24 * ((jc1 * 1311) >> 15);
        float t0 = fmaf(sacc[nt][0], SL2, BL[add0 - sub0]);
        float t1 = fmaf(sacc[nt][1], SL2, BL[add0 - sub1]);
        float t2 = fmaf(sacc[nt][2], SL2, BL[add1 - sub0]);
        float t3 = fmaf(sacc[nt][3], SL2, BL[add1 - sub1]);
        if (LAST) {
            if (jg0 >= 625) { t0 = -1e30f; t2 = -1e30f; }
            if (jg1 >= 625) { t1 = -1e30f; t3 = -1e30f; }
        }
        pha[nt][0] = ex2_bf16x2(pack2bf(t0, t1));
        pha[nt][1] = ex2_bf16x2(pack2bf(t2, t3));
    }

    // ---- row sums: lacc += P * ones ----
#pragma unroll
    for (int kc2 = 0; kc2 < 4; kc2++)
        mma16816(lacc, pha[2 * kc2][0], pha[2 * kc2][1],
                 pha[2 * kc2 + 1][0], pha[2 * kc2 + 1][1], ONES, ONES);

    // ---- O += P V ----
#pragma unroll
    for (int p2 = 0; p2 < 2; p2++) {
#pragma unroll
        for (int kc2 = 0; kc2 < 4; kc2++) {
            uint32_t d0, d1, d2, d3;
            ldm_x4t(d0, d1, d2, d3, Vb + (kc2 * 16 + arow) * SBK + p2 * 32 + kh);
            mma16816(oacc[2 * p2],     pha[2 * kc2][0], pha[2 * kc2][1],
                     pha[2 * kc2 + 1][0], pha[2 * kc2 + 1][1], d0, d1);
            mma16816(oacc[2 * p2 + 1], pha[2 * kc2][0], pha[2 * kc2][1],
                     pha[2 * kc2 + 1][0], pha[2 * kc2 + 1][1], d2, d3);
        }
    }
}

__global__ __launch_bounds__(256, 3) void attn_tc(const ush* __restrict__ qh_,
                                                  const float* __restrict__ tT,
                                                  ush* __restrict__ oh)
{
    __shared__ uint32_t QHI[128 * SROW];
    __shared__ uint32_t KHI[2 * KVB];
    __shared__ uint32_t VHI[2 * KVB];
    __shared__ float    BL[TBL];

    const int head = blockIdx.x;
    const int win  = blockIdx.y;
    const int qt   = blockIdx.z;
    const int tid  = threadIdx.x;
    const int w = tid >> 5, lane = tid & 31;
    const int g = lane >> 2, t = tid & 3;
    const int tok0 = win * 625;
    const int qbase = qt * 128;
    const int arow = (lane & 7) + ((lane >> 3) & 1) * 8;
    const int kh = (lane >> 4) * 16;
    const uint32_t Kb0 = smem_u32(KHI);
    const uint32_t Vb0 = smem_u32(VHI);

    const int lrr = tid >> 2, lcc = tid & 3;
#define KV_ISSUE(kb) do {                                                        \
    int _jg = (kb) * 64 + lrr; if (_jg > 624) _jg = 624;                          \
    size_t _src = (size_t)(tok0 + _jg) * QKVN + head * 32 + lcc * 8;              \
    uint32_t _off = ((kb) & 1) * (KVB * 4) + lrr * SBK + lcc * 16;                \
    CP_ASYNC16(Kb0 + _off, qh_ + _src + 256);                                     \
    CP_ASYNC16(Vb0 + _off, qh_ + _src + 512);                                     \
} while (0)

    KV_ISSUE(0); CP_COMMIT();

    // coalesced: table already transposed + pre-scaled by log2(e)
    const float* tH = tT + head * TBL;
    for (int i = tid; i < TBL; i += 256) BL[i] = tH[i];

#pragma unroll
    for (int it = 0; it < 2; it++) {
        int idx = it * 256 + tid;
        int r = idx >> 2, c = idx & 3;
        int qi = qbase + r;
        uint4 v = make_uint4(0, 0, 0, 0);
        if (qi < 625)
            v = *(const uint4*)(qh_ + (size_t)(tok0 + qi) * QKVN + head * 32 + c * 8);
        *(uint4*)(QHI + r * SROW + c * 4) = v;
    }
    __syncthreads();

    uint32_t qh[2][4];
    {
        int r0 = w * 16 + g;
#pragma unroll
        for (int kc = 0; kc < 2; kc++) {
            qh[kc][0] = QHI[r0 * SROW + kc * 8 + t];
            qh[kc][1] = QHI[(r0 + 8) * SROW + kc * 8 + t];
            qh[kc][2] = QHI[r0 * SROW + kc * 8 + t + 4];
            qh[kc][3] = QHI[(r0 + 8) * SROW + kc * 8 + t + 4];
        }
    }

    const int qi0 = qbase + w * 16 + g;
    const int qi1 = qi0 + 8;
    const int cq0 = qi0 < 625 ? qi0 : 624;
    const int cq1 = qi1 < 625 ? qi1 : 624;
    const int add0 = (cq0 / 25 + 24) * 49 + (cq0 % 25) + 24;
    const int add1 = (cq1 / 25 + 24) * 49 + (cq1 % 25) + 24;

    float lacc[4] = {0.f, 0.f, 0.f, 0.f};
    float oacc[4][4];
#pragma unroll
    for (int i = 0; i < 4; i++)
#pragma unroll
        for (int j = 0; j < 4; j++) oacc[i][j] = 0.f;

#pragma unroll 1
    for (int kb = 0; kb < 9; kb++) {
        CP_WAIT0();
        __syncthreads();
        KV_ISSUE(kb + 1); CP_COMMIT();
        attn_compute<false>(kb, t, arow, kh,
                            Kb0 + (kb & 1) * (KVB * 4),
                            Vb0 + (kb & 1) * (KVB * 4),
                            BL, add0, add1, qh, lacc, oacc);
    }
    CP_WAIT0();
    __syncthreads();
    attn_compute<true>(9, t, arow, kh,
                       Kb0 + (9 & 1) * (KVB * 4),
                       Vb0 + (9 & 1) * (KVB * 4),
                       BL, add0, add1, qh, lacc, oacc);
#undef KV_ISSUE

    float inv0 = 1.f / lacc[0], inv1 = 1.f / lacc[2];

    if (qi0 < 625) {
        size_t o = (size_t)(tok0 + qi0) * DCH + head * 32;
#pragma unroll
        for (int nt2 = 0; nt2 < 4; nt2++) {
            int d = nt2 * 8 + 2 * t;
            *(uint32_t*)(oh + o + d) = pack2bf(oacc[nt2][0] * inv0,
                                               oacc[nt2][1] * inv0);
        }
    }
    if (qi1 < 625) {
        size_t o = (size_t)(tok0 + qi1) * DCH + head * 32;
#pragma unroll
        for (int nt2 = 0; nt2 < 4; nt2++) {
            int d = nt2 * 8 + 2 * t;
            *(uint32_t*)(oh + o + d) = pack2bf(oacc[nt2][2] * inv1,
                                               oacc[nt2][3] * inv1);
        }
    }
}

// ---------------------------------------------------------------------------
// LayerNorm over d=256: one warp per token; bf16 in -> bf16 out
// ---------------------------------------------------------------------------
__global__ __launch_bounds__(256) void ln_kernel(const ush* __restrict__ in,
                                                 ush* __restrict__ oh,
                                                 const float* __restrict__ g,
                                                 const float* __restrict__ b)
{
    int wid = threadIdx.x >> 5, lane = threadIdx.x & 31;
    int t = blockIdx.x * 8 + wid;
    const uint2* p = (const uint2*)(in + (size_t)t * DCH);
    uint2 a = p[lane];
    uint2 c = p[lane + 32];
    float f0 = lo_bf(a.x), f1 = hi_bf(a.x), f2 = lo_bf(a.y), f3 = hi_bf(a.y);
    float f4 = lo_bf(c.x), f5 = hi_bf(c.x), f6 = lo_bf(c.y), f7 = hi_bf(c.y);

    float s  = f0 + f1 + f2 + f3 + f4 + f5 + f6 + f7;
    float ss = f0 * f0 + f1 * f1 + f2 * f2 + f3 * f3
             + f4 * f4 + f5 * f5 + f6 * f6 + f7 * f7;
#pragma unroll
    for (int off = 16; off > 0; off >>= 1) {
        s  += __shfl_xor_sync(0xffffffffu, s, off);
        ss += __shfl_xor_sync(0xffffffffu, ss, off);
    }
    float mean = s * (1.f / 256.f);
    float var  = ss * (1.f / 256.f) - mean * mean;
    float rstd = rsqrtf(var + 1e-5f);

    const float4* g4 = (const float4*)g;
    const float4* b4 = (const float4*)b;
    float4 ga = g4[lane], gb = g4[lane + 32];
    float4 ba = b4[lane], bb = b4[lane + 32];

    uint2 o0, o1;
    o0.x = pack2bf((f0 - mean) * rstd * ga.x + ba.x,
                   (f1 - mean) * rstd * ga.y + ba.y);
    o0.y = pack2bf((f2 - mean) * rstd * ga.z + ba.z,
                   (f3 - mean) * rstd * ga.w + ba.w);
    o1.x = pack2bf((f4 - mean) * rstd * gb.x + bb.x,
                   (f5 - mean) * rstd * gb.y + bb.y);
    o1.y = pack2bf((f6 - mean) * rstd * gb.z + bb.z,
                   (f7 - mean) * rstd * gb.w + bb.w);

    size_t o = (size_t)t * DCH;
    *(uint2*)(oh + o + lane * 4)       = o0;
    *(uint2*)(oh + o + 128 + lane * 4) = o1;
}

// ---------------------------------------------------------------------------
extern "C" void kernel_launch(void* const* d_in, const int* in_sizes, int n_in,
                              void* d_out, int out_size)
{
    const float* x      = (const float*)d_in[0];
    const float* w_qkv  = (const float*)d_in[1];
    const float* w_out  = (const float*)d_in[2];
    const float* table  = (const float*)d_in[3];
    const float* gamma2 = (const float*)d_in[4];
    const float* beta2  = (const float*)d_in[5];
    const float* w1     = (const float*)d_in[6];
    const float* b1     = (const float*)d_in[7];
    const float* w2     = (const float*)d_in[8];
    const float* b2     = (const float*)d_in[9];
    float* out = (float*)d_out;

    ush *xw, *qkv, *att, *ln, *hid, *wv;
    float *tT;
    cudaGetSymbolAddress((void**)&xw,  g_xw);
    cudaGetSymbolAddress((void**)&qkv, g_qkv);
    cudaGetSymbolAddress((void**)&att, g_att);
    cudaGetSymbolAddress((void**)&ln,  g_ln);
    cudaGetSymbolAddress((void**)&hid, g_hid);
    cudaGetSymbolAddress((void**)&wv,  g_w);
    cudaGetSymbolAddress((void**)&tT,  g_tableT);

    cudaFuncSetAttribute(gemm_tc, cudaFuncAttributeMaxDynamicSharedMemorySize, GEMM_SMEM);

    // 0) weights -> bf16 plane + table transpose (one launch)
    prep_kernel<<<(WTOT + TTOT + 1023) / 1024, 256>>>(w_qkv, w_out, w1, w2,
                                                      table, wv, tT);

    // 1) window partition (transposed, coalesced)
    gather_kernel<<<dim3(625, 8), 256>>>(x, xw);
    // 2) QKV projection -> bf16
    gemm_tc<<<dim3(12, 157), 256, GEMM_SMEM>>>(xw, wv + WQ,
        TOK, QKVN, DCH, 3, nullptr, nullptr, nullptr, qkv);
    // 3) tensor-core windowed attention -> bf16
    attn_tc<<<dim3(8, 32, 5), 256>>>(qkv, tT, att);
    // 4) output projection -> bf16 (reuses g_xw)
    gemm_tc<<<dim3(4, 157), 256, GEMM_SMEM>>>(att, wv + WO,
        TOK, DCH, DCH, 3, nullptr, nullptr, nullptr, xw);
    // 5) layernorm (bf16 in) -> bf16
    ln_kernel<<<2500, 256>>>(xw, ln, gamma2, beta2);
    // 6) MLP fc1 + exact GELU -> bf16
    gemm_tc<<<dim3(8, 157), 256, GEMM_SMEM>>>(ln, wv + W1,
        TOK, HID, DCH, 1, b1, nullptr, nullptr, hid);
    // 7) MLP fc2 + bias + un-partition + residual -> d_out (fused scatter)
    gemm_tc<<<dim3(4, 157), 256, GEMM_SMEM>>>(hid, wv + W2,
        TOK, DCH, HID, 2, b2, x, out, nullptr);
}

// round 16
// speedup vs baseline: 1.3849x; 1.0631x over previous
#include <cuda_runtime.h>
#include <cuda_bf16.h>
#include <cstdint>
#include <math.h>

#define TOK 20000      // 2 * 16 windows * 625 tokens
#define DCH 256
#define QKVN 768
#define HID 512

typedef unsigned short ush;

// ---- scratch: plain bf16 planes ----
__device__ ush g_xw  [TOK * DCH];   // gather out / QKV in ; later out-proj out
__device__ ush g_qkv [TOK * QKVN];
__device__ ush g_att [TOK * DCH];   // attn out / out-proj in
__device__ ush g_ln  [TOK * DCH];
__device__ ush g_hid [TOK * HID];
// all four weight matrices concatenated: wqkv | wout | w1 | w2
#define WQ 0
#define WO 196608
#define W1 262144
#define W2 393216
#define WTOT 524288
__device__ ush g_w[WTOT];
// rel-pos bias table transposed per-head and pre-scaled by log2(e)
#define TBL 2401
__device__ float g_tableT[8 * TBL];

// ---------------------------------------------------------------------------
// helpers
// ---------------------------------------------------------------------------
__device__ __forceinline__ uint32_t smem_u32(const void* p) {
    uint32_t a;
    asm("{ .reg .u64 t; cvta.to.shared.u64 t, %1; cvt.u32.u64 %0, t; }" : "=r"(a) : "l"(p));
    return a;
}
#define CP_ASYNC16(dst, src) \
    asm volatile("cp.async.cg.shared.global [%0], [%1], 16;" :: "r"(dst), "l"(src))
#define CP_COMMIT() asm volatile("cp.async.commit_group;")
#define CP_WAIT0()  asm volatile("cp.async.wait_group 0;")

__device__ __forceinline__ void ldm_x4(uint32_t& d0, uint32_t& d1, uint32_t& d2,
                                       uint32_t& d3, uint32_t addr)
{
    asm volatile("ldmatrix.sync.aligned.m8n8.x4.shared.b16 {%0,%1,%2,%3}, [%4];"
                 : "=r"(d0), "=r"(d1), "=r"(d2), "=r"(d3) : "r"(addr));
}
__device__ __forceinline__ void ldm_x4t(uint32_t& d0, uint32_t& d1, uint32_t& d2,
                                        uint32_t& d3, uint32_t addr)
{
    asm volatile("ldmatrix.sync.aligned.m8n8.x4.trans.shared.b16 {%0,%1,%2,%3}, [%4];"
                 : "=r"(d0), "=r"(d1), "=r"(d2), "=r"(d3) : "r"(addr));
}

__device__ __forceinline__ void mma16816(float c[4], uint32_t a0, uint32_t a1,
                                         uint32_t a2, uint32_t a3,
                                         uint32_t b0, uint32_t b1)
{
    asm volatile(
        "mma.sync.aligned.m16n8k16.row.col.f32.bf16.bf16.f32 "
        "{%0,%1,%2,%3}, {%4,%5,%6,%7}, {%8,%9}, {%0,%1,%2,%3};"
        : "+f"(c[0]), "+f"(c[1]), "+f"(c[2]), "+f"(c[3])
        : "r"(a0), "r"(a1), "r"(a2), "r"(a3), "r"(b0), "r"(b1));
}

__device__ __forceinline__ ush bfr(float f) {
    return __bfloat16_as_ushort(__float2bfloat16_rn(f));
}
// pack 2 floats -> bf16x2 in ONE cvt (lo = first arg)
__device__ __forceinline__ uint32_t pack2bf(float lo, float hi) {
    uint32_t r;
    asm("cvt.rn.bf16x2.f32 %0, %1, %2;" : "=r"(r) : "f"(hi), "f"(lo));
    return r;
}
// packed exp2 on bf16x2
__device__ __forceinline__ uint32_t ex2_bf16x2(uint32_t x) {
    uint32_t r;
    asm("ex2.approx.ftz.bf16x2 %0, %1;" : "=r"(r) : "r"(x));
    return r;
}
__device__ __forceinline__ float lo_bf(uint32_t w) { return __uint_as_float(w << 16); }
__device__ __forceinline__ float hi_bf(uint32_t w) { return __uint_as_float(w & 0xFFFF0000u); }

__device__ __forceinline__ float gelu_exact(float v)
{
    return 0.5f * v * (1.0f + erff(v * 0.70710678118654752f));
}

// ---------------------------------------------------------------------------
// merged prep: weight conversion + rel-bias table transpose (pre-scaled)
// ---------------------------------------------------------------------------
#define TTOT (8 * TBL)
__global__ __launch_bounds__(256) void prep_kernel(
    const float* __restrict__ s0, const float* __restrict__ s1,
    const float* __restrict__ s2, const float* __restrict__ s3,
    const float* __restrict__ table,
    ush* __restrict__ h, float* __restrict__ tT)
{
    int base = (blockIdx.x * blockDim.x + threadIdx.x) * 4;
    if (base < WTOT) {
        const float* src;
        int off;
        if (base < WO)      { src = s0; off = base; }
        else if (base < W1) { src = s1; off = base - WO; }
        else if (base < W2) { src = s2; off = base - W1; }
        else                { src = s3; off = base - W2; }
        float4 v = *(const float4*)(src + off);
        uint2 o;
        o.x = pack2bf(v.x, v.y);
        o.y = pack2bf(v.z, v.w);
        *(uint2*)(h + base) = o;
    } else {
        int ti = base - WTOT;   // over 8*2401 entries of table (row-major 2401x8)
#pragma unroll
        for (int j = 0; j < 4; j++) {
            int idx = ti + j;
            if (idx < TTOT) {
                int pos = idx >> 3, head = idx & 7;
                tT[head * TBL + pos] = table[idx] * 1.4426950408889634f;
            }
        }
    }
}

// ---------------------------------------------------------------------------
// window partition with smem transpose: x (2,256,100,100) -> bf16 (20000,256)
// ---------------------------------------------------------------------------
__global__ __launch_bounds__(256) void gather_kernel(const float* __restrict__ x,
                                                     ush* __restrict__ xh)
{
    __shared__ float sm[32][33];
    const int w = threadIdx.x >> 5, lane = threadIdx.x & 31;
    const int tk0 = blockIdx.x * 32;
    const int ch0 = blockIdx.y * 32;

    {
        int tk = tk0 + lane;
        int bb = tk / 10000, rr = tk % 10000;
        int win = rr / 625, t = rr % 625;
        int hh = (win >> 2) * 25 + t / 25;
        int ww = (win & 3) * 25 + t % 25;
        int base = bb * 2560000 + hh * 100 + ww;
#pragma unroll
        for (int i = 0; i < 4; i++) {
            int ch = ch0 + w * 4 + i;
            sm[w * 4 + i][lane] = x[base + ch * 10000];
        }
    }
    __syncthreads();

#pragma unroll
    for (int i = 0; i < 4; i++) {
        int tl = w * 4 + i;
        xh[(size_t)(tk0 + tl) * DCH + ch0 + lane] = bfr(sm[lane][tl]);
    }
}

// ---------------------------------------------------------------------------
// plain-bf16 tensor-core GEMM: tile 128x64, warp 32x32, 3 CTAs/SM,
// BK=64, double-buffered cp.async + ldmatrix.
// mode 1: gelu(C+bias)->bf16  mode 2: scatter+residual (fp32)  mode 3: C->bf16
// ---------------------------------------------------------------------------
#define SB    144         // smem row stride bytes (128 data + 16 pad)
#define PLBA  18432       // A tile: 128 rows * SB
#define PLBB  9216        // B tile: 64 rows * SB
#define BUFB  27648       // A + B
#define NSTG  2
#define GEMM_SMEM (NSTG * BUFB)

__global__ __launch_bounds__(256, 3) void gemm_tc(
    const ush* __restrict__ Ah, const ush* __restrict__ Bh,
    int M, int N, int K, int mode,
    const float* __restrict__ bias, const float* __restrict__ xres,
    float* __restrict__ outF, ush* __restrict__ oh)
{
    extern __shared__ char smem[];
    const uint32_t sbb = smem_u32(smem);
    const int tid = threadIdx.x;
    const int wid = tid >> 5, lane = tid & 31;
    const int g = lane >> 2, t = lane & 3;
    const int wm = (wid & 3) * 32;
    const int wn = (wid >> 2) * 32;
    const int row0 = blockIdx.y * 128, coln0 = blockIdx.x * 64;

    float acc[2][4][4];
#pragma unroll
    for (int i = 0; i < 2; i++)
#pragma unroll
        for (int j = 0; j < 4; j++)
#pragma unroll
            for (int q = 0; q < 4; q++) acc[i][j][q] = 0.f;

    const int nst = K >> 6;   // BK = 64

    // loader: A = 1024 16B-chunks (4/thread), B = 512 (2/thread); c fixed/thread
    const int lrb = tid >> 3, lc = tid & 7;
    int ar[4], br[2];
#pragma unroll
    for (int i = 0; i < 4; i++) {
        int r = i * 32 + lrb;
        int gr = row0 + r;
        ar[i] = gr > M - 1 ? M - 1 : gr;
    }
#pragma unroll
    for (int i = 0; i < 2; i++)
        br[i] = coln0 + i * 32 + lrb;

#define ISSUE(s) do {                                                          \
    int _b = (s) & 1;                                                          \
    int _k0 = (s) << 6;                                                        \
    uint32_t _da = sbb + _b * BUFB + lrb * SB + lc * 16;                       \
    CP_ASYNC16(_da,                   Ah + (size_t)ar[0] * K + _k0 + lc * 8);  \
    CP_ASYNC16(_da + 32 * SB,         Ah + (size_t)ar[1] * K + _k0 + lc * 8);  \
    CP_ASYNC16(_da + 64 * SB,         Ah + (size_t)ar[2] * K + _k0 + lc * 8);  \
    CP_ASYNC16(_da + 96 * SB,         Ah + (size_t)ar[3] * K + _k0 + lc * 8);  \
    uint32_t _db = _da + PLBA;                                                 \
    CP_ASYNC16(_db,                   Bh + (size_t)br[0] * K + _k0 + lc * 8);  \
    CP_ASYNC16(_db + 32 * SB,         Bh + (size_t)br[1] * K + _k0 + lc * 8);  \
} while (0)

    ISSUE(0); CP_COMMIT();

    const int arow = (lane & 7) + ((lane >> 3) & 1) * 8;
    const int kh = (lane >> 4) * 16;

    for (int s = 0; s < nst; s++) {
        CP_WAIT0();
        __syncthreads();            // stage s visible; prior compute done
        if (s + 1 < nst) { ISSUE(s + 1); CP_COMMIT(); }

        const uint32_t pa = sbb + (s & 1) * BUFB;
        const uint32_t pb = pa + PLBA;
#pragma unroll
        for (int ks = 0; ks < 4; ks++) {
            const uint32_t cb = ks * 32 + kh;
            uint32_t ah[2][4];
#pragma unroll
            for (int mt = 0; mt < 2; mt++) {
                uint32_t ad = pa + (wm + mt * 16 + arow) * SB + cb;
                ldm_x4(ah[mt][0], ah[mt][1], ah[mt][2], ah[mt][3], ad);
            }
            uint32_t bh[4][2];
#pragma unroll
            for (int p = 0; p < 2; p++) {
                uint32_t bd = pb + (wn + p * 16 + arow) * SB + cb;
                ldm_x4(bh[2 * p][0], bh[2 * p + 1][0], bh[2 * p][1], bh[2 * p + 1][1], bd);
            }
#pragma unroll
            for (int mt = 0; mt < 2; mt++)
#pragma unroll
                for (int nt = 0; nt < 4; nt++)
                    mma16816(acc[mt][nt], ah[mt][0], ah[mt][1], ah[mt][2], ah[mt][3],
                             bh[nt][0], bh[nt][1]);
        }
        __syncthreads();            // compute done before next ISSUE overwrites
    }
#undef ISSUE

    // ---- epilogue ----
#pragma unroll
    for (int mt = 0; mt < 2; mt++) {
#pragma unroll
        for (int half = 0; half < 2; half++) {
            int r = row0 + wm + mt * 16 + g + half * 8;
            if (r >= M) continue;
#pragma unroll
            for (int nt = 0; nt < 4; nt++) {
                int col = coln0 + wn + nt * 8 + 2 * t;
                float v0 = acc[mt][nt][half * 2 + 0];
                float v1 = acc[mt][nt][half * 2 + 1];
                if (mode == 3) {
                    *(uint32_t*)(oh + (size_t)r * N + col) = pack2bf(v0, v1);
                } else if (mode == 1) {
                    *(uint32_t*)(oh + (size_t)r * N + col) =
                        pack2bf(gelu_exact(v0 + bias[col]),
                                gelu_exact(v1 + bias[col + 1]));
                } else { // mode 2: scatter + residual
                    int bb = r / 10000, rr = r % 10000;
                    int win = rr / 625, tt = rr % 625;
                    int hh2 = (win >> 2) * 25 + tt / 25;
                    int ww = (win & 3) * 25 + tt % 25;
                    int obase = bb * 2560000 + hh2 * 100 + ww;
                    int oi0 = obase + col * 10000;
                    int oi1 = obase + (col + 1) * 10000;
                    outF[oi0] = xres[oi0] + v0 + bias[col];
                    outF[oi1] = xres[oi1] + v1 + bias[col + 1];
                }
            }
        }
    }
}

// ---------------------------------------------------------------------------
// tensor-core windowed attention: bf16, cp.async double-buffered K/V,
// ldmatrix (V via .trans), packed-bf16 exp, row-sum via mma-with-ones.
// grid = (head 8, win 32, qtile 5); CTA 256 thr; 3 CTAs/SM enforced.
// ---------------------------------------------------------------------------
#define SROW 20
#define SBK  80     // row stride bytes for K/V tiles
#define KVB  (64 * SROW)    // one K or V tile in words
#define SL2  0.25503487f    // (1/sqrt(32)) * log2(e)
#define ONES 0x3F803F80u    // bf16x2 {1.0, 1.0}

template<bool LAST>
__device__ __forceinline__ void attn_compute(
    int kb, int t, int arow, int kh,
    uint32_t Kb, uint32_t Vb,
    const float* BL, int add0, int add1,
    const uint32_t qh[2][4], float lacc[4], float oacc[4][4])
{
    // ---- S = Q K^T ----
    float sacc[8][4];
#pragma unroll
    for (int i = 0; i < 8; i++)
#pragma unroll
        for (int j = 0; j < 4; j++) sacc[i][j] = 0.f;

#pragma unroll
    for (int p = 0; p < 4; p++) {
        uint32_t base = Kb + (p * 16 + arow) * SBK + kh;
        uint32_t kA0, kA1, kA2, kA3, kB0, kB1, kB2, kB3;
        ldm_x4(kA0, kA1, kA2, kA3, base);
        ldm_x4(kB0, kB1, kB2, kB3, base + 32);
        mma16816(sacc[2 * p],     qh[0][0], qh[0][1], qh[0][2], qh[0][3], kA0, kA2);
        mma16816(sacc[2 * p + 1], qh[0][0], qh[0][1], qh[0][2], qh[0][3], kA1, kA3);
        mma16816(sacc[2 * p],     qh[1][0], qh[1][1], qh[1][2], qh[1][3], kB0, kB2);
        mma16816(sacc[2 * p + 1], qh[1][0], qh[1][1], qh[1][2], qh[1][3], kB1, kB3);
    }

    // ---- bias + packed bf16 ex2 ----
    const int kbase = kb * 64;
    uint32_t pha[8][2];
#pragma unroll
    for (int nt = 0; nt < 8; nt++) {
        int jl0 = nt * 8 + 2 * t;
        int jg0 = kbase + jl0;
        int jg1 = jg0 + 1;
        int jc0 = LAST ? (jg0 < 624 ? jg0 : 624) : jg0;
        int jc1 = LAST ? (jg1 < 624 ? jg1 : 624) : jg1;
        int sub0 = jc0 + 24 * ((jc0 * 1311) >> 15);
        int sub1 = jc1 + 24 * ((jc1 * 1311) >> 15);
        float t0 = fmaf(sacc[nt][0], SL2, BL[add0 - sub0]);
        float t1 = fmaf(sacc[nt][1], SL2, BL[add0 - sub1]);
        float t2 = fmaf(sacc[nt][2], SL2, BL[add1 - sub0]);
        float t3 = fmaf(sacc[nt][3], SL2, BL[add1 - sub1]);
        if (LAST) {
            if (jg0 >= 625) { t0 = -1e30f; t2 = -1e30f; }
            if (jg1 >= 625) { t1 = -1e30f; t3 = -1e30f; }
        }
        pha[nt][0] = ex2_bf16x2(pack2bf(t0, t1));
        pha[nt][1] = ex2_bf16x2(pack2bf(t2, t3));
    }

    // ---- row sums: lacc += P * ones ----
#pragma unroll
    for (int kc2 = 0; kc2 < 4; kc2++)
        mma16816(lacc, pha[2 * kc2][0], pha[2 * kc2][1],
                 pha[2 * kc2 + 1][0], pha[2 * kc2 + 1][1], ONES, ONES);

    // ---- O += P V ----
#pragma unroll
    for (int p2 = 0; p2 < 2; p2++) {
#pragma unroll
        for (int kc2 = 0; kc2 < 4; kc2++) {
            uint32_t d0, d1, d2, d3;
            ldm_x4t(d0, d1, d2, d3, Vb + (kc2 * 16 + arow) * SBK + p2 * 32 + kh);
            mma16816(oacc[2 * p2],     pha[2 * kc2][0], pha[2 * kc2][1],
                     pha[2 * kc2 + 1][0], pha[2 * kc2 + 1][1], d0, d1);
            mma16816(oacc[2 * p2 + 1], pha[2 * kc2][0], pha[2 * kc2][1],
                     pha[2 * kc2 + 1][0], pha[2 * kc2 + 1][1], d2, d3);
        }
    }
}

__global__ __launch_bounds__(256, 3) void attn_tc(const ush* __restrict__ qh_,
                                                  const float* __restrict__ tT,
                                                  ush* __restrict__ oh)
{
    __shared__ uint32_t QHI[128 * SROW];
    __shared__ uint32_t KHI[2 * KVB];
    __shared__ uint32_t VHI[2 * KVB];
    __shared__ float    BL[TBL];

    const int head = blockIdx.x;
    const int win  = blockIdx.y;
    const int qt   = blockIdx.z;
    const int tid  = threadIdx.x;
    const int w = tid >> 5, lane = tid & 31;
    const int g = lane >> 2, t = tid & 3;
    const int tok0 = win * 625;
    const int qbase = qt * 128;
    const int arow = (lane & 7) + ((lane >> 3) & 1) * 8;
    const int kh = (lane >> 4) * 16;
    const uint32_t Kb0 = smem_u32(KHI);
    const uint32_t Vb0 = smem_u32(VHI);

    const int lrr = tid >> 2, lcc = tid & 3;
#define KV_ISSUE(kb) do {                                                        \
    int _jg = (kb) * 64 + lrr; if (_jg > 624) _jg = 624;                          \
    size_t _src = (size_t)(tok0 + _jg) * QKVN + head * 32 + lcc * 8;              \
    uint32_t _off = ((kb) & 1) * (KVB * 4) + lrr * SBK + lcc * 16;                \
    CP_ASYNC16(Kb0 + _off, qh_ + _src + 256);                                     \
    CP_ASYNC16(Vb0 + _off, qh_ + _src + 512);                                     \
} while (0)

    KV_ISSUE(0); CP_COMMIT();

    // coalesced: table already transposed + pre-scaled by log2(e)
    const float* tH = tT + head * TBL;
    for (int i = tid; i < TBL; i += 256) BL[i] = tH[i];

#pragma unroll
    for (int it = 0; it < 2; it++) {
        int idx = it * 256 + tid;
        int r = idx >> 2, c = idx & 3;
        int qi = qbase + r;
        uint4 v = make_uint4(0, 0, 0, 0);
        if (qi < 625)
            v = *(const uint4*)(qh_ + (size_t)(tok0 + qi) * QKVN + head * 32 + c * 8);
        *(uint4*)(QHI + r * SROW + c * 4) = v;
    }
    __syncthreads();

    uint32_t qh[2][4];
    {
        int r0 = w * 16 + g;
#pragma unroll
        for (int kc = 0; kc < 2; kc++) {
            qh[kc][0] = QHI[r0 * SROW + kc * 8 + t];
            qh[kc][1] = QHI[(r0 + 8) * SROW + kc * 8 + t];
            qh[kc][2] = QHI[r0 * SROW + kc * 8 + t + 4];
            qh[kc][3] = QHI[(r0 + 8) * SROW + kc * 8 + t + 4];
        }
    }

    const int qi0 = qbase + w * 16 + g;
    const int qi1 = qi0 + 8;
    const int cq0 = qi0 < 625 ? qi0 : 624;
    const int cq1 = qi1 < 625 ? qi1 : 624;
    const int add0 = (cq0 / 25 + 24) * 49 + (cq0 % 25) + 24;
    const int add1 = (cq1 / 25 + 24) * 49 + (cq1 % 25) + 24;

    float lacc[4] = {0.f, 0.f, 0.f, 0.f};
    float oacc[4][4];
#pragma unroll
    for (int i = 0; i < 4; i++)
#pragma unroll
        for (int j = 0; j < 4; j++) oacc[i][j] = 0.f;

#pragma unroll 1
    for (int kb = 0; kb < 9; kb++) {
        CP_WAIT0();
        __syncthreads();
        KV_ISSUE(kb + 1); CP_COMMIT();
        attn_compute<false>(kb, t, arow, kh,
                            Kb0 + (kb & 1) * (KVB * 4),
                            Vb0 + (kb & 1) * (KVB * 4),
                            BL, add0, add1, qh, lacc, oacc);
    }
    CP_WAIT0();
    __syncthreads();
    attn_compute<true>(9, t, arow, kh,
                       Kb0 + (9 & 1) * (KVB * 4),
                       Vb0 + (9 & 1) * (KVB * 4),
                       BL, add0, add1, qh, lacc, oacc);
#undef KV_ISSUE

    float inv0 = 1.f / lacc[0], inv1 = 1.f / lacc[2];

    if (qi0 < 625) {
        size_t o = (size_t)(tok0 + qi0) * DCH + head * 32;
#pragma unroll
        for (int nt2 = 0; nt2 < 4; nt2++) {
            int d = nt2 * 8 + 2 * t;
            *(uint32_t*)(oh + o + d) = pack2bf(oacc[nt2][0] * inv0,
                                               oacc[nt2][1] * inv0);
        }
    }
    if (qi1 < 625) {
        size_t o = (size_t)(tok0 + qi1) * DCH + head * 32;
#pragma unroll
        for (int nt2 = 0; nt2 < 4; nt2++) {
            int d = nt2 * 8 + 2 * t;
            *(uint32_t*)(oh + o + d) = pack2bf(oacc[nt2][2] * inv1,
                                               oacc[nt2][3] * inv1);
        }
    }
}

// ---------------------------------------------------------------------------
// LayerNorm over d=256: one warp per token; bf16 in -> bf16 out
// ---------------------------------------------------------------------------
__global__ __launch_bounds__(256) void ln_kernel(const ush* __restrict__ in,
                                                 ush* __restrict__ oh,
                                                 const float* __restrict__ g,
                                                 const float* __restrict__ b)
{
    int wid = threadIdx.x >> 5, lane = threadIdx.x & 31;
    int t = blockIdx.x * 8 + wid;
    const uint2* p = (const uint2*)(in + (size_t)t * DCH);
    uint2 a = p[lane];
    uint2 c = p[lane + 32];
    float f0 = lo_bf(a.x), f1 = hi_bf(a.x), f2 = lo_bf(a.y), f3 = hi_bf(a.y);
    float f4 = lo_bf(c.x), f5 = hi_bf(c.x), f6 = lo_bf(c.y), f7 = hi_bf(c.y);

    float s  = f0 + f1 + f2 + f3 + f4 + f5 + f6 + f7;
    float ss = f0 * f0 + f1 * f1 + f2 * f2 + f3 * f3
             + f4 * f4 + f5 * f5 + f6 * f6 + f7 * f7;
#pragma unroll
    for (int off = 16; off > 0; off >>= 1) {
        s  += __shfl_xor_sync(0xffffffffu, s, off);
        ss += __shfl_xor_sync(0xffffffffu, ss, off);
    }
    float mean = s * (1.f / 256.f);
    float var  = ss * (1.f / 256.f) - mean * mean;
    float rstd = rsqrtf(var + 1e-5f);

    const float4* g4 = (const float4*)g;
    const float4* b4 = (const float4*)b;
    float4 ga = g4[lane], gb = g4[lane + 32];
    float4 ba = b4[lane], bb = b4[lane + 32];

    uint2 o0, o1;
    o0.x = pack2bf((f0 - mean) * rstd * ga.x + ba.x,
                   (f1 - mean) * rstd * ga.y + ba.y);
    o0.y = pack2bf((f2 - mean) * rstd * ga.z + ba.z,
                   (f3 - mean) * rstd * ga.w + ba.w);
    o1.x = pack2bf((f4 - mean) * rstd * gb.x + bb.x,
                   (f5 - mean) * rstd * gb.y + bb.y);
    o1.y = pack2bf((f6 - mean) * rstd * gb.z + bb.z,
                   (f7 - mean) * rstd * gb.w + bb.w);

    size_t o = (size_t)t * DCH;
    *(uint2*)(oh + o + lane * 4)       = o0;
    *(uint2*)(oh + o + 128 + lane * 4) = o1;
}

// ---------------------------------------------------------------------------
extern "C" void kernel_launch(void* const* d_in, const int* in_sizes, int n_in,
                              void* d_out, int out_size)
{
    const float* x      = (const float*)d_in[0];
    const float* w_qkv  = (const float*)d_in[1];
    const float* w_out  = (const float*)d_in[2];
    const float* table  = (const float*)d_in[3];
    const float* gamma2 = (const float*)d_in[4];
    const float* beta2  = (const float*)d_in[5];
    const float* w1     = (const float*)d_in[6];
    const float* b1     = (const float*)d_in[7];
    const float* w2     = (const float*)d_in[8];
    const float* b2     = (const float*)d_in[9];
    float* out = (float*)d_out;

    ush *xw, *qkv, *att, *ln, *hid, *wv;
    float *tT;
    cudaGetSymbolAddress((void**)&xw,  g_xw);
    cudaGetSymbolAddress((void**)&qkv, g_qkv);
    cudaGetSymbolAddress((void**)&att, g_att);
    cudaGetSymbolAddress((void**)&ln,  g_ln);
    cudaGetSymbolAddress((void**)&hid, g_hid);
    cudaGetSymbolAddress((void**)&wv,  g_w);
    cudaGetSymbolAddress((void**)&tT,  g_tableT);

    cudaFuncSetAttribute(gemm_tc, cudaFuncAttributeMaxDynamicSharedMemorySize, GEMM_SMEM);

    // 0) weights -> bf16 plane + table transpose (one launch)
    prep_kernel<<<(WTOT + TTOT + 1023) / 1024, 256>>>(w_qkv, w_out, w1, w2,
                                                      table, wv, tT);

    // 1) window partition (transposed, coalesced)
    gather_kernel<<<dim3(625, 8), 256>>>(x, xw);
    // 2) QKV projection -> bf16
    gemm_tc<<<dim3(12, 157), 256, GEMM_SMEM>>>(xw, wv + WQ,
        TOK, QKVN, DCH, 3, nullptr, nullptr, nullptr, qkv);
    // 3) tensor-core windowed attention -> bf16
    attn_tc<<<dim3(8, 32, 5), 256>>>(qkv, tT, att);
    // 4) output projection -> bf16 (reuses g_xw)
    gemm_tc<<<dim3(4, 157), 256, GEMM_SMEM>>>(att, wv + WO,
        TOK, DCH, DCH, 3, nullptr, nullptr, nullptr, xw);
    // 5) layernorm (bf16 in) -> bf16
    ln_kernel<<<2500, 256>>>(xw, ln, gamma2, beta2);
    // 6) MLP fc1 + exact GELU -> bf16
    gemm_tc<<<dim3(8, 157), 256, GEMM_SMEM>>>(ln, wv + W1,
        TOK, HID, DCH, 1, b1, nullptr, nullptr, hid);
    // 7) MLP fc2 + bias + un-partition + residual -> d_out (fused scatter)
    gemm_tc<<<dim3(4, 157), 256, GEMM_SMEM>>>(hid, wv + W2,
        TOK, DCH, HID, 2, b2, x, out, nullptr);
}